// round 4
// baseline (speedup 1.0000x reference)
#include <cuda_runtime.h>
#include <math.h>

#define DIMC   128
#define NF     64
#define NG     50
#define NBINS  32768
#define DMAXF  16.0f
#define MAXN   100352
#define LOG2C  0.69314718055994531f
#define CUTOFFF 10.0f

// ---------------- scratch (static device arrays; no runtime alloc) ----------------
__device__ float g_h  [(size_t)MAXN * NF];     // x @ conv_lin1_w   [N,64]
__device__ float g_agg[(size_t)MAXN * NF];     // segment-summed messages [N,64]
__device__ float g_tab[(size_t)NBINS * NF];    // W(d)*C(d) lookup table
__device__ int   g_is64;                       // 1 if edge_index buffer is int64

__device__ __forceinline__ float sspf(float v) {
    // shifted softplus, numerically stable: log(1+e^v) - log2
    return fmaxf(v, 0.0f) + log1pf(__expf(-fabsf(v))) - LOG2C;
}

// ---------------- kernel 0a: zero the aggregation buffer --------------------------
__global__ void zero_agg_kernel(int n) {
    int total = n * (NF / 4);
    int idx = blockIdx.x * blockDim.x + threadIdx.x;
    if (idx < total)
        ((float4*)g_agg)[idx] = make_float4(0.f, 0.f, 0.f, 0.f);
}

// ---------------- kernel 0b: detect edge_index dtype ------------------------------
// int64 little-endian indices in [0,n) always read as int32 pairs (lo in [0,n), hi==0).
// Genuine int32 index data fails this on the first nonzero odd word (~immediately).
__global__ void detect_dtype_kernel(const int* __restrict__ ei, int E, int n) {
    __shared__ int bad;
    if (threadIdx.x == 0) bad = 0;
    __syncthreads();
    for (int i = threadIdx.x; i < 1024; i += blockDim.x) {
        long long e = ((long long)i * (long long)E) / 1024LL;
        int lo = ei[2 * e];
        int hi = ei[2 * e + 1];
        if (hi != 0 || lo < 0 || lo >= n) atomicExch(&bad, 1);
    }
    __syncthreads();
    if (threadIdx.x == 0) g_is64 = bad ? 0 : 1;
}

// ---------------- kernel 1: build W(d)*C(d) table --------------------------------
// T[bin][f] = ( ssp(gauss(d) @ w1 + b1) @ w2 + b2 )[f] * 0.5*(cos(pi*d/10)+1)
__global__ void build_table_kernel(const float* __restrict__ w1, const float* __restrict__ b1,
                                   const float* __restrict__ w2, const float* __restrict__ b2) {
    __shared__ float w1s[NG * NF];
    __shared__ float w2s[NF * NF];
    __shared__ float b1s[NF], b2s[NF];
    __shared__ float attr[4][NG];
    __shared__ float f1s [4][NF];

    int tid = threadIdx.x;
    for (int i = tid; i < NG * NF; i += 256) w1s[i] = w1[i];
    for (int i = tid; i < NF * NF; i += 256) w2s[i] = w2[i];
    if (tid < NF) { b1s[tid] = b1[tid]; b2s[tid] = b2[tid]; }
    __syncthreads();

    const int grp = tid >> 6;       // 4 bins per block pass
    const int f   = tid & 63;
    const float delta    = DMAXF / (float)(NBINS - 1);
    const float off_step = CUTOFFF / (float)(NG - 1);
    const float coeff    = -0.5f / (off_step * off_step);

    for (int base = blockIdx.x * 4; base < NBINS; base += gridDim.x * 4) {
        int bin = base + grp;
        float d = (float)bin * delta;

        if (f < NG) {
            float t = d - (float)f * off_step;
            attr[grp][f] = __expf(coeff * t * t);
        }
        __syncthreads();

        float z = b1s[f];
        #pragma unroll
        for (int g = 0; g < NG; g++) z += attr[grp][g] * w1s[g * NF + f];
        f1s[grp][f] = sspf(z);
        __syncthreads();

        float wv = b2s[f];
        #pragma unroll
        for (int i = 0; i < NF; i++) wv += f1s[grp][i] * w2s[i * NF + f];

        float C = 0.5f * (cosf(d * 0.31415926535897932f) + 1.0f);
        g_tab[(size_t)bin * NF + f] = wv * C;
        __syncthreads();   // protect attr/f1s before next pass
    }
}

// ---------------- kernel 2: node embed h = x @ conv_lin1_w  [N,64] ----------------
__global__ void embed_kernel(const float* __restrict__ x, const float* __restrict__ w, int n) {
    __shared__ float4 ws[DIMC * 16];       // w[k][f] as float4 groups: ws[k*16+fg]
    __shared__ float  xs[16][DIMC];

    int tid = threadIdx.x;
    for (int i = tid; i < DIMC * 16; i += 256) ws[i] = ((const float4*)w)[i];

    const int fg = tid & 15;               // 16 float4 groups -> 64 outputs
    const int ng = tid >> 4;               // 16 nodes per pass
    const int ntiles = (n + 15) >> 4;

    for (int tile = blockIdx.x; tile < ntiles; tile += gridDim.x) {
        int node0 = tile << 4;
        __syncthreads();                   // protect xs + first-iter ws
        for (int i = tid; i < 512; i += 256) {
            int r = i >> 5, c = i & 31;
            int node = node0 + r;
            float4 v = (node < n) ? ((const float4*)x)[(size_t)node * 32 + c]
                                  : make_float4(0.f, 0.f, 0.f, 0.f);
            ((float4*)xs[r])[c] = v;
        }
        __syncthreads();

        float4 acc = make_float4(0.f, 0.f, 0.f, 0.f);
        #pragma unroll 8
        for (int k = 0; k < DIMC; k++) {
            float  xv = xs[ng][k];
            float4 wv = ws[k * 16 + fg];
            acc.x += xv * wv.x; acc.y += xv * wv.y;
            acc.z += xv * wv.z; acc.w += xv * wv.w;
        }
        int node = node0 + ng;
        if (node < n) ((float4*)g_h)[(size_t)node * 16 + fg] = acc;
    }
}

// ---------------- kernel 3: per-edge message + scatter ----------------------------
// 16 threads per edge; each thread handles 4 filters (float4 loads, scalar atomics).
// Index dtype chosen at runtime via g_is64. Indices clamped (IMA-proof either way).
__global__ void edge_kernel(const int* __restrict__ ei,
                            const float* __restrict__ pos, int E, int n) {
    unsigned long long idx = (unsigned long long)blockIdx.x * blockDim.x + threadIdx.x;
    int e   = (int)(idx >> 4);
    int sub = (int)(idx & 15);
    if (e >= E) return;

    int src, dst;
    if (g_is64) {                       // int64 buffer: low words at even int32 offsets
        src = ei[2 * (size_t)e];
        dst = ei[2 * ((size_t)E + e)];
    } else {                            // int32 buffer
        src = ei[e];
        dst = ei[(size_t)E + e];
    }
    src = min(max(src, 0), n - 1);
    dst = min(max(dst, 0), n - 1);

    float dx = pos[dst * 3 + 0] - pos[src * 3 + 0];
    float dy = pos[dst * 3 + 1] - pos[src * 3 + 1];
    float dz = pos[dst * 3 + 2] - pos[src * 3 + 2];
    float d  = sqrtf(dx * dx + dy * dy + dz * dz);

    float u = d * ((float)(NBINS - 1) / DMAXF);
    if (u > (float)(NBINS - 1)) u = (float)(NBINS - 1);
    int i0 = (int)u;
    if (i0 > NBINS - 2) i0 = NBINS - 2;
    if (i0 < 0) i0 = 0;
    float fr = u - (float)i0;

    const float4* t0 = ((const float4*)g_tab) + (size_t)i0 * 16 + sub;
    float4 a = t0[0];
    float4 b = t0[16];
    float4 w;
    w.x = a.x + fr * (b.x - a.x);
    w.y = a.y + fr * (b.y - a.y);
    w.z = a.z + fr * (b.z - a.z);
    w.w = a.w + fr * (b.w - a.w);

    float4 hs = ((const float4*)g_h)[(size_t)src * 16 + sub];

    float* dstp = g_agg + (size_t)dst * NF + sub * 4;
    atomicAdd(dstp + 0, hs.x * w.x);
    atomicAdd(dstp + 1, hs.y * w.y);
    atomicAdd(dstp + 2, hs.z * w.z);
    atomicAdd(dstp + 3, hs.w * w.w);
}

// ---------------- kernel 4: fused node tail ---------------------------------------
// h2 = ssp(agg @ wA + bA)  [N,128]
// h3 = h2 @ wB + bB        [N,128]
// out = x + relu(h3 @ wC + bC)
// All weights in dynamic smem; 4-node register tile per thread.
#define TAIL_SMEM_FLOATS (8192 + 16384 + 16384 + 384 + 2048 + 4096 + 4096)
#define TAIL_SMEM_BYTES  (TAIL_SMEM_FLOATS * 4)

__global__ void tail_kernel(const float* __restrict__ x,
                            const float* __restrict__ wA, const float* __restrict__ bA,
                            const float* __restrict__ wB, const float* __restrict__ bB,
                            const float* __restrict__ wC, const float* __restrict__ bC,
                            float* __restrict__ out, int n) {
    extern __shared__ float sm[];
    float* wAs   = sm;                  // [64*128]
    float* wBs   = wAs + 8192;          // [128*128]
    float* wCs   = wBs + 16384;         // [128*128]
    float* bAs   = wCs + 16384;         // [128]
    float* bBs   = bAs + 128;
    float* bCs   = bBs + 128;
    float* aggs  = bCs + 128;           // [32][64]
    float* h2s   = aggs + 2048;         // [32][128]
    float* h3s   = h2s + 4096;          // [32][128]

    int tid = threadIdx.x;
    for (int i = tid; i < 8192;  i += 256) wAs[i] = wA[i];
    for (int i = tid; i < 16384; i += 256) { wBs[i] = wB[i]; wCs[i] = wC[i]; }
    if (tid < 128) { bAs[tid] = bA[tid]; bBs[tid] = bB[tid]; bCs[tid] = bC[tid]; }

    const int fg  = tid & 31;           // 32 float4 groups -> 128 outputs
    const int grp = tid >> 5;           // 8 groups x 4 nodes = 32-node tile
    const int ntiles = (n + 31) >> 5;
    const float4 biasA = make_float4(bA[fg*4+0], bA[fg*4+1], bA[fg*4+2], bA[fg*4+3]);
    const float4 biasB = make_float4(bB[fg*4+0], bB[fg*4+1], bB[fg*4+2], bB[fg*4+3]);
    const float4 biasC = make_float4(bC[fg*4+0], bC[fg*4+1], bC[fg*4+2], bC[fg*4+3]);

    for (int tile = blockIdx.x; tile < ntiles; tile += gridDim.x) {
        int node0 = tile << 5;
        __syncthreads();                // protect smem tiles from previous pass
        // load agg tile [32][64] : 512 float4
        for (int i = tid; i < 512; i += 256) {
            int r = i >> 4, c = i & 15;
            int node = node0 + r;
            float4 v = (node < n) ? ((const float4*)g_agg)[(size_t)node * 16 + c]
                                  : make_float4(0.f, 0.f, 0.f, 0.f);
            ((float4*)(aggs + r * 64))[c] = v;
        }
        __syncthreads();

        // ---- stage A: [32,64] @ [64,128] + bA -> ssp -> h2s ----
        {
            float4 acc0 = biasA, acc1 = biasA, acc2 = biasA, acc3 = biasA;
            const float* inr0 = aggs + (grp * 4 + 0) * 64;
            const float* inr1 = aggs + (grp * 4 + 1) * 64;
            const float* inr2 = aggs + (grp * 4 + 2) * 64;
            const float* inr3 = aggs + (grp * 4 + 3) * 64;
            #pragma unroll 4
            for (int i = 0; i < 64; i++) {
                float4 w = ((const float4*)wAs)[i * 32 + fg];
                float a0 = inr0[i], a1 = inr1[i], a2 = inr2[i], a3 = inr3[i];
                acc0.x += a0*w.x; acc0.y += a0*w.y; acc0.z += a0*w.z; acc0.w += a0*w.w;
                acc1.x += a1*w.x; acc1.y += a1*w.y; acc1.z += a1*w.z; acc1.w += a1*w.w;
                acc2.x += a2*w.x; acc2.y += a2*w.y; acc2.z += a2*w.z; acc2.w += a2*w.w;
                acc3.x += a3*w.x; acc3.y += a3*w.y; acc3.z += a3*w.z; acc3.w += a3*w.w;
            }
            float4* o0 = (float4*)(h2s + (grp * 4 + 0) * 128) + fg;
            float4* o1 = (float4*)(h2s + (grp * 4 + 1) * 128) + fg;
            float4* o2 = (float4*)(h2s + (grp * 4 + 2) * 128) + fg;
            float4* o3 = (float4*)(h2s + (grp * 4 + 3) * 128) + fg;
            *o0 = make_float4(sspf(acc0.x), sspf(acc0.y), sspf(acc0.z), sspf(acc0.w));
            *o1 = make_float4(sspf(acc1.x), sspf(acc1.y), sspf(acc1.z), sspf(acc1.w));
            *o2 = make_float4(sspf(acc2.x), sspf(acc2.y), sspf(acc2.z), sspf(acc2.w));
            *o3 = make_float4(sspf(acc3.x), sspf(acc3.y), sspf(acc3.z), sspf(acc3.w));
        }
        __syncthreads();

        // ---- stage B: [32,128] @ [128,128] + bB -> h3s ----
        {
            float4 acc0 = biasB, acc1 = biasB, acc2 = biasB, acc3 = biasB;
            const float* inr0 = h2s + (grp * 4 + 0) * 128;
            const float* inr1 = h2s + (grp * 4 + 1) * 128;
            const float* inr2 = h2s + (grp * 4 + 2) * 128;
            const float* inr3 = h2s + (grp * 4 + 3) * 128;
            #pragma unroll 4
            for (int i = 0; i < 128; i++) {
                float4 w = ((const float4*)wBs)[i * 32 + fg];
                float a0 = inr0[i], a1 = inr1[i], a2 = inr2[i], a3 = inr3[i];
                acc0.x += a0*w.x; acc0.y += a0*w.y; acc0.z += a0*w.z; acc0.w += a0*w.w;
                acc1.x += a1*w.x; acc1.y += a1*w.y; acc1.z += a1*w.z; acc1.w += a1*w.w;
                acc2.x += a2*w.x; acc2.y += a2*w.y; acc2.z += a2*w.z; acc2.w += a2*w.w;
                acc3.x += a3*w.x; acc3.y += a3*w.y; acc3.z += a3*w.z; acc3.w += a3*w.w;
            }
            ((float4*)(h3s + (grp * 4 + 0) * 128))[fg] = acc0;
            ((float4*)(h3s + (grp * 4 + 1) * 128))[fg] = acc1;
            ((float4*)(h3s + (grp * 4 + 2) * 128))[fg] = acc2;
            ((float4*)(h3s + (grp * 4 + 3) * 128))[fg] = acc3;
        }
        __syncthreads();

        // ---- stage C: [32,128] @ [128,128] + bC -> relu -> + x -> out ----
        {
            float4 acc0 = biasC, acc1 = biasC, acc2 = biasC, acc3 = biasC;
            const float* inr0 = h3s + (grp * 4 + 0) * 128;
            const float* inr1 = h3s + (grp * 4 + 1) * 128;
            const float* inr2 = h3s + (grp * 4 + 2) * 128;
            const float* inr3 = h3s + (grp * 4 + 3) * 128;
            #pragma unroll 4
            for (int i = 0; i < 128; i++) {
                float4 w = ((const float4*)wCs)[i * 32 + fg];
                float a0 = inr0[i], a1 = inr1[i], a2 = inr2[i], a3 = inr3[i];
                acc0.x += a0*w.x; acc0.y += a0*w.y; acc0.z += a0*w.z; acc0.w += a0*w.w;
                acc1.x += a1*w.x; acc1.y += a1*w.y; acc1.z += a1*w.z; acc1.w += a1*w.w;
                acc2.x += a2*w.x; acc2.y += a2*w.y; acc2.z += a2*w.z; acc2.w += a2*w.w;
                acc3.x += a3*w.x; acc3.y += a3*w.y; acc3.z += a3*w.z; acc3.w += a3*w.w;
            }
            #pragma unroll
            for (int r = 0; r < 4; r++) {
                int node = node0 + grp * 4 + r;
                if (node >= n) continue;
                float4 acc = (r == 0) ? acc0 : (r == 1) ? acc1 : (r == 2) ? acc2 : acc3;
                float4 xv = ((const float4*)x)[(size_t)node * 32 + fg];
                float4 o;
                o.x = xv.x + fmaxf(acc.x, 0.f);
                o.y = xv.y + fmaxf(acc.y, 0.f);
                o.z = xv.z + fmaxf(acc.z, 0.f);
                o.w = xv.w + fmaxf(acc.w, 0.f);
                ((float4*)out)[(size_t)node * 32 + fg] = o;
            }
        }
    }
}

// ---------------- launcher --------------------------------------------------------
extern "C" void kernel_launch(void* const* d_in, const int* in_sizes, int n_in,
                              void* d_out, int out_size) {
    const float* x        = (const float*)d_in[0];
    const float* pos      = (const float*)d_in[1];
    const int*   ei       = (const int*)d_in[2];     // dtype detected at runtime
    const float* mlp_w1   = (const float*)d_in[3];
    const float* mlp_b1   = (const float*)d_in[4];
    const float* mlp_w2   = (const float*)d_in[5];
    const float* mlp_b2   = (const float*)d_in[6];
    const float* conv1_w  = (const float*)d_in[7];
    const float* conv2_w  = (const float*)d_in[8];
    const float* conv2_b  = (const float*)d_in[9];
    const float* int_w    = (const float*)d_in[10];
    const float* int_b    = (const float*)d_in[11];
    const float* lin1_w   = (const float*)d_in[12];
    const float* lin1_b   = (const float*)d_in[13];
    float*       out      = (float*)d_out;

    int n = in_sizes[0] / DIMC;
    int E = in_sizes[2] / 2;
    if (n > MAXN) n = MAXN;

    // zero the aggregation buffer + detect index dtype (both graph-capturable kernels)
    {
        int total = n * (NF / 4);
        zero_agg_kernel<<<(total + 255) / 256, 256>>>(n);
        detect_dtype_kernel<<<1, 256>>>(ei, E, n);
    }

    build_table_kernel<<<512, 256>>>(mlp_w1, mlp_b1, mlp_w2, mlp_b2);
    embed_kernel<<<296, 256>>>(x, conv1_w, n);

    unsigned long long ethreads = (unsigned long long)E * 16ULL;
    unsigned int eblocks = (unsigned int)((ethreads + 255ULL) / 256ULL);
    edge_kernel<<<eblocks, 256>>>(ei, pos, E, n);

    static_assert(TAIL_SMEM_BYTES <= 224 * 1024, "tail smem too large");
    cudaFuncSetAttribute(tail_kernel, cudaFuncAttributeMaxDynamicSharedMemorySize,
                         TAIL_SMEM_BYTES);
    tail_kernel<<<148, 256, TAIL_SMEM_BYTES>>>(x, conv2_w, conv2_b, int_w, int_b,
                                               lin1_w, lin1_b, out, n);
}

// round 5
// speedup vs baseline: 1.3265x; 1.3265x over previous
#include <cuda_runtime.h>
#include <math.h>

#define DIMC   128
#define NF     64
#define NG     50
#define NBINS  32768
#define DMAXF  16.0f
#define MAXN   100352
#define LOG2C  0.69314718055994531f
#define CUTOFFF 10.0f

// ---------------- scratch (static device arrays; no runtime alloc) ----------------
// float4-typed for guaranteed 16B alignment (vector loads + red.global.v4).
__device__ float4 g_h4  [(size_t)MAXN * 16];    // x @ conv_lin1_w   [N,64]
__device__ float4 g_agg4[(size_t)MAXN * 16];    // segment-summed messages [N,64]
__device__ float4 g_tab4[(size_t)NBINS * 16];   // W(d)*C(d) lookup table [NBINS,64]
__device__ int    g_is64;                       // 1 if edge_index buffer is int64

__device__ __forceinline__ float sspf(float v) {
    return fmaxf(v, 0.0f) + log1pf(__expf(-fabsf(v))) - LOG2C;
}

// ---------------- kernel 0a: zero the aggregation buffer --------------------------
__global__ void zero_agg_kernel(int n) {
    int total = n * 16;
    int idx = blockIdx.x * blockDim.x + threadIdx.x;
    if (idx < total)
        g_agg4[idx] = make_float4(0.f, 0.f, 0.f, 0.f);
}

// ---------------- kernel 0b: detect edge_index dtype ------------------------------
__global__ void detect_dtype_kernel(const int* __restrict__ ei, int E, int n) {
    __shared__ int bad;
    if (threadIdx.x == 0) bad = 0;
    __syncthreads();
    for (int i = threadIdx.x; i < 1024; i += blockDim.x) {
        long long e = ((long long)i * (long long)E) / 1024LL;
        int lo = ei[2 * e];
        int hi = ei[2 * e + 1];
        if (hi != 0 || lo < 0 || lo >= n) atomicExch(&bad, 1);
    }
    __syncthreads();
    if (threadIdx.x == 0) g_is64 = bad ? 0 : 1;
}

// ---------------- kernel 1: build W(d)*C(d) table --------------------------------
__global__ void build_table_kernel(const float* __restrict__ w1, const float* __restrict__ b1,
                                   const float* __restrict__ w2, const float* __restrict__ b2) {
    __shared__ float w1s[NG * NF];
    __shared__ float w2s[NF * NF];
    __shared__ float b1s[NF], b2s[NF];
    __shared__ float attr[4][NG];
    __shared__ float f1s [4][NF];

    int tid = threadIdx.x;
    for (int i = tid; i < NG * NF; i += 256) w1s[i] = w1[i];
    for (int i = tid; i < NF * NF; i += 256) w2s[i] = w2[i];
    if (tid < NF) { b1s[tid] = b1[tid]; b2s[tid] = b2[tid]; }
    __syncthreads();

    const int grp = tid >> 6;
    const int f   = tid & 63;
    const float delta    = DMAXF / (float)(NBINS - 1);
    const float off_step = CUTOFFF / (float)(NG - 1);
    const float coeff    = -0.5f / (off_step * off_step);
    float* tab = (float*)g_tab4;

    for (int base = blockIdx.x * 4; base < NBINS; base += gridDim.x * 4) {
        int bin = base + grp;
        float d = (float)bin * delta;

        if (f < NG) {
            float t = d - (float)f * off_step;
            attr[grp][f] = __expf(coeff * t * t);
        }
        __syncthreads();

        float z = b1s[f];
        #pragma unroll
        for (int g = 0; g < NG; g++) z += attr[grp][g] * w1s[g * NF + f];
        f1s[grp][f] = sspf(z);
        __syncthreads();

        float wv = b2s[f];
        #pragma unroll
        for (int i = 0; i < NF; i++) wv += f1s[grp][i] * w2s[i * NF + f];

        float C = 0.5f * (cosf(d * 0.31415926535897932f) + 1.0f);
        tab[(size_t)bin * NF + f] = wv * C;
        __syncthreads();
    }
}

// ---------------- kernel 2: node embed h = x @ conv_lin1_w  [N,64] ----------------
// k-vectorized (float4 over k) + 4-node register tile: 8 LDS.128 per 64 FFMA.
#define ETILE 64
#define EMBED_SMEM_BYTES ((DIMC * 16 + ETILE * 32) * 16)   // ws 32KB + xs 32KB

__global__ void embed_kernel(const float* __restrict__ x, const float* __restrict__ w, int n) {
    extern __shared__ float4 esm[];
    float4* ws = esm;                 // [DIMC*16] : ws[k*16+fg] = w[k][4fg..4fg+3]
    float4* xs = esm + DIMC * 16;     // [ETILE*32]: node-major rows of 32 float4

    int tid = threadIdx.x;
    for (int i = tid; i < DIMC * 16; i += 256) ws[i] = ((const float4*)w)[i];

    const int fg = tid & 15;          // 16 output float4 groups
    const int nr = tid >> 4;          // 16 thread rows x 4 nodes = 64 nodes/tile
    const int ntiles = (n + ETILE - 1) / ETILE;

    for (int tile = blockIdx.x; tile < ntiles; tile += gridDim.x) {
        int node0 = tile * ETILE;
        __syncthreads();
        for (int i = tid; i < ETILE * 32; i += 256) {
            int node = node0 + (i >> 5);
            xs[i] = (node < n) ? ((const float4*)x)[(size_t)node * 32 + (i & 31)]
                               : make_float4(0.f, 0.f, 0.f, 0.f);
        }
        __syncthreads();

        float4 acc0 = make_float4(0.f,0.f,0.f,0.f), acc1 = acc0, acc2 = acc0, acc3 = acc0;
        const float4* xr0 = xs + (nr * 4 + 0) * 32;
        const float4* xr1 = xs + (nr * 4 + 1) * 32;
        const float4* xr2 = xs + (nr * 4 + 2) * 32;
        const float4* xr3 = xs + (nr * 4 + 3) * 32;

        #pragma unroll 4
        for (int k4 = 0; k4 < 32; k4++) {
            float4 w0 = ws[(k4 * 4 + 0) * 16 + fg];
            float4 w1 = ws[(k4 * 4 + 1) * 16 + fg];
            float4 w2 = ws[(k4 * 4 + 2) * 16 + fg];
            float4 w3 = ws[(k4 * 4 + 3) * 16 + fg];
            float4 a0 = xr0[k4], a1 = xr1[k4], a2 = xr2[k4], a3 = xr3[k4];

            acc0.x += a0.x*w0.x + a0.y*w1.x + a0.z*w2.x + a0.w*w3.x;
            acc0.y += a0.x*w0.y + a0.y*w1.y + a0.z*w2.y + a0.w*w3.y;
            acc0.z += a0.x*w0.z + a0.y*w1.z + a0.z*w2.z + a0.w*w3.z;
            acc0.w += a0.x*w0.w + a0.y*w1.w + a0.z*w2.w + a0.w*w3.w;

            acc1.x += a1.x*w0.x + a1.y*w1.x + a1.z*w2.x + a1.w*w3.x;
            acc1.y += a1.x*w0.y + a1.y*w1.y + a1.z*w2.y + a1.w*w3.y;
            acc1.z += a1.x*w0.z + a1.y*w1.z + a1.z*w2.z + a1.w*w3.z;
            acc1.w += a1.x*w0.w + a1.y*w1.w + a1.z*w2.w + a1.w*w3.w;

            acc2.x += a2.x*w0.x + a2.y*w1.x + a2.z*w2.x + a2.w*w3.x;
            acc2.y += a2.x*w0.y + a2.y*w1.y + a2.z*w2.y + a2.w*w3.y;
            acc2.z += a2.x*w0.z + a2.y*w1.z + a2.z*w2.z + a2.w*w3.z;
            acc2.w += a2.x*w0.w + a2.y*w1.w + a2.z*w2.w + a2.w*w3.w;

            acc3.x += a3.x*w0.x + a3.y*w1.x + a3.z*w2.x + a3.w*w3.x;
            acc3.y += a3.x*w0.y + a3.y*w1.y + a3.z*w2.y + a3.w*w3.y;
            acc3.z += a3.x*w0.z + a3.y*w1.z + a3.z*w2.z + a3.w*w3.z;
            acc3.w += a3.x*w0.w + a3.y*w1.w + a3.z*w2.w + a3.w*w3.w;
        }

        #pragma unroll
        for (int r = 0; r < 4; r++) {
            int node = node0 + nr * 4 + r;
            if (node >= n) continue;
            float4 a = (r == 0) ? acc0 : (r == 1) ? acc1 : (r == 2) ? acc2 : acc3;
            g_h4[(size_t)node * 16 + fg] = a;
        }
    }
}

// ---------------- kernel 3: per-edge message + scatter ----------------------------
// 16 threads/edge (2 edges/warp). Lane 0 of each 16-group loads idx/pos, computes
// the bin coordinate; broadcast via shfl. Scatter = one red.global.add.v4.f32.
__global__ void edge_kernel(const int* __restrict__ ei,
                            const float* __restrict__ pos, int E, int n) {
    int lane = threadIdx.x & 31;
    int sub  = lane & 15;
    long long warp = ((long long)blockIdx.x * blockDim.x + threadIdx.x) >> 5;
    long long e = warp * 2 + (lane >> 4);
    bool valid = (e < (long long)E);

    int src = 0, dst = 0; float u = 0.f;
    if (sub == 0 && valid) {
        if (g_is64) { src = ei[2 * (size_t)e]; dst = ei[2 * ((size_t)E + e)]; }
        else        { src = ei[(size_t)e];     dst = ei[(size_t)E + e];       }
        src = min(max(src, 0), n - 1);
        dst = min(max(dst, 0), n - 1);
        float dx = pos[dst * 3 + 0] - pos[src * 3 + 0];
        float dy = pos[dst * 3 + 1] - pos[src * 3 + 1];
        float dz = pos[dst * 3 + 2] - pos[src * 3 + 2];
        float d  = sqrtf(dx * dx + dy * dy + dz * dz);
        u = d * ((float)(NBINS - 1) / DMAXF);
        u = fminf(u, (float)(NBINS - 1));
    }
    src = __shfl_sync(0xffffffffu, src, 0, 16);
    dst = __shfl_sync(0xffffffffu, dst, 0, 16);
    u   = __shfl_sync(0xffffffffu, u,   0, 16);
    if (!valid) return;

    int i0 = (int)u;
    if (i0 > NBINS - 2) i0 = NBINS - 2;
    float fr = u - (float)i0;

    const float4* t0 = g_tab4 + (size_t)i0 * 16 + sub;
    float4 a = t0[0];
    float4 b = t0[16];
    float4 wv;
    wv.x = fmaf(fr, b.x - a.x, a.x);
    wv.y = fmaf(fr, b.y - a.y, a.y);
    wv.z = fmaf(fr, b.z - a.z, a.z);
    wv.w = fmaf(fr, b.w - a.w, a.w);

    float4 hs = g_h4[(size_t)src * 16 + sub];
    float4 m;
    m.x = hs.x * wv.x; m.y = hs.y * wv.y; m.z = hs.z * wv.z; m.w = hs.w * wv.w;

    float4* dstp = g_agg4 + (size_t)dst * 16 + sub;
    asm volatile("{ .reg .u64 ga; cvta.to.global.u64 ga, %0; "
                 "red.global.add.v4.f32 [ga], {%1, %2, %3, %4}; }"
                 :: "l"(dstp), "f"(m.x), "f"(m.y), "f"(m.z), "f"(m.w) : "memory");
}

// ---------------- kernel 4: fused node tail ---------------------------------------
// h2 = ssp(agg @ wA + bA); h3 = h2 @ wB + bB; out = x + relu(h3 @ wC + bC)
// i-vectorized inner loops: 8 LDS.128 per 64 FFMA.
#define TAIL_SMEM_FLOATS (8192 + 16384 + 16384 + 2048 + 4096 + 4096)
#define TAIL_SMEM_BYTES  (TAIL_SMEM_FLOATS * 4)

__global__ void tail_kernel(const float* __restrict__ x,
                            const float* __restrict__ wA, const float* __restrict__ bA,
                            const float* __restrict__ wB, const float* __restrict__ bB,
                            const float* __restrict__ wC, const float* __restrict__ bC,
                            float* __restrict__ out, int n) {
    extern __shared__ float sm[];
    float* wAs   = sm;                  // [64*128]
    float* wBs   = wAs + 8192;          // [128*128]
    float* wCs   = wBs + 16384;         // [128*128]
    float* aggs  = wCs + 16384;         // [32][64]
    float* h2s   = aggs + 2048;         // [32][128]
    float* h3s   = h2s + 4096;          // [32][128]

    int tid = threadIdx.x;
    for (int i = tid; i < 8192;  i += 256) wAs[i] = wA[i];
    for (int i = tid; i < 16384; i += 256) { wBs[i] = wB[i]; wCs[i] = wC[i]; }

    const int fg  = tid & 31;           // 32 float4 groups -> 128 outputs
    const int grp = tid >> 5;           // 8 groups x 4 nodes = 32-node tile
    const int ntiles = (n + 31) >> 5;
    const float4 biasA = make_float4(bA[fg*4+0], bA[fg*4+1], bA[fg*4+2], bA[fg*4+3]);
    const float4 biasB = make_float4(bB[fg*4+0], bB[fg*4+1], bB[fg*4+2], bB[fg*4+3]);
    const float4 biasC = make_float4(bC[fg*4+0], bC[fg*4+1], bC[fg*4+2], bC[fg*4+3]);

    for (int tile = blockIdx.x; tile < ntiles; tile += gridDim.x) {
        int node0 = tile << 5;
        __syncthreads();
        for (int i = tid; i < 512; i += 256) {
            int r = i >> 4, c = i & 15;
            int node = node0 + r;
            float4 v = (node < n) ? g_agg4[(size_t)node * 16 + c]
                                  : make_float4(0.f, 0.f, 0.f, 0.f);
            ((float4*)(aggs + r * 64))[c] = v;
        }
        __syncthreads();

        // ---- stage A: [32,64] @ [64,128] + bA -> ssp -> h2s ----
        {
            float4 acc0 = biasA, acc1 = biasA, acc2 = biasA, acc3 = biasA;
            const float4* in0 = (const float4*)(aggs + (grp * 4 + 0) * 64);
            const float4* in1 = (const float4*)(aggs + (grp * 4 + 1) * 64);
            const float4* in2 = (const float4*)(aggs + (grp * 4 + 2) * 64);
            const float4* in3 = (const float4*)(aggs + (grp * 4 + 3) * 64);
            const float4* wv = (const float4*)wAs;
            #pragma unroll 4
            for (int i4 = 0; i4 < 16; i4++) {
                float4 w0 = wv[(i4*4+0)*32+fg], w1 = wv[(i4*4+1)*32+fg];
                float4 w2 = wv[(i4*4+2)*32+fg], w3 = wv[(i4*4+3)*32+fg];
                float4 a0 = in0[i4], a1 = in1[i4], a2 = in2[i4], a3 = in3[i4];
                acc0.x += a0.x*w0.x + a0.y*w1.x + a0.z*w2.x + a0.w*w3.x;
                acc0.y += a0.x*w0.y + a0.y*w1.y + a0.z*w2.y + a0.w*w3.y;
                acc0.z += a0.x*w0.z + a0.y*w1.z + a0.z*w2.z + a0.w*w3.z;
                acc0.w += a0.x*w0.w + a0.y*w1.w + a0.z*w2.w + a0.w*w3.w;
                acc1.x += a1.x*w0.x + a1.y*w1.x + a1.z*w2.x + a1.w*w3.x;
                acc1.y += a1.x*w0.y + a1.y*w1.y + a1.z*w2.y + a1.w*w3.y;
                acc1.z += a1.x*w0.z + a1.y*w1.z + a1.z*w2.z + a1.w*w3.z;
                acc1.w += a1.x*w0.w + a1.y*w1.w + a1.z*w2.w + a1.w*w3.w;
                acc2.x += a2.x*w0.x + a2.y*w1.x + a2.z*w2.x + a2.w*w3.x;
                acc2.y += a2.x*w0.y + a2.y*w1.y + a2.z*w2.y + a2.w*w3.y;
                acc2.z += a2.x*w0.z + a2.y*w1.z + a2.z*w2.z + a2.w*w3.z;
                acc2.w += a2.x*w0.w + a2.y*w1.w + a2.z*w2.w + a2.w*w3.w;
                acc3.x += a3.x*w0.x + a3.y*w1.x + a3.z*w2.x + a3.w*w3.x;
                acc3.y += a3.x*w0.y + a3.y*w1.y + a3.z*w2.y + a3.w*w3.y;
                acc3.z += a3.x*w0.z + a3.y*w1.z + a3.z*w2.z + a3.w*w3.z;
                acc3.w += a3.x*w0.w + a3.y*w1.w + a3.z*w2.w + a3.w*w3.w;
            }
            ((float4*)(h2s + (grp*4+0)*128))[fg] = make_float4(sspf(acc0.x), sspf(acc0.y), sspf(acc0.z), sspf(acc0.w));
            ((float4*)(h2s + (grp*4+1)*128))[fg] = make_float4(sspf(acc1.x), sspf(acc1.y), sspf(acc1.z), sspf(acc1.w));
            ((float4*)(h2s + (grp*4+2)*128))[fg] = make_float4(sspf(acc2.x), sspf(acc2.y), sspf(acc2.z), sspf(acc2.w));
            ((float4*)(h2s + (grp*4+3)*128))[fg] = make_float4(sspf(acc3.x), sspf(acc3.y), sspf(acc3.z), sspf(acc3.w));
        }
        __syncthreads();

        // ---- stage B: [32,128] @ [128,128] + bB -> h3s ----
        {
            float4 acc0 = biasB, acc1 = biasB, acc2 = biasB, acc3 = biasB;
            const float4* in0 = (const float4*)(h2s + (grp * 4 + 0) * 128);
            const float4* in1 = (const float4*)(h2s + (grp * 4 + 1) * 128);
            const float4* in2 = (const float4*)(h2s + (grp * 4 + 2) * 128);
            const float4* in3 = (const float4*)(h2s + (grp * 4 + 3) * 128);
            const float4* wv = (const float4*)wBs;
            #pragma unroll 4
            for (int i4 = 0; i4 < 32; i4++) {
                float4 w0 = wv[(i4*4+0)*32+fg], w1 = wv[(i4*4+1)*32+fg];
                float4 w2 = wv[(i4*4+2)*32+fg], w3 = wv[(i4*4+3)*32+fg];
                float4 a0 = in0[i4], a1 = in1[i4], a2 = in2[i4], a3 = in3[i4];
                acc0.x += a0.x*w0.x + a0.y*w1.x + a0.z*w2.x + a0.w*w3.x;
                acc0.y += a0.x*w0.y + a0.y*w1.y + a0.z*w2.y + a0.w*w3.y;
                acc0.z += a0.x*w0.z + a0.y*w1.z + a0.z*w2.z + a0.w*w3.z;
                acc0.w += a0.x*w0.w + a0.y*w1.w + a0.z*w2.w + a0.w*w3.w;
                acc1.x += a1.x*w0.x + a1.y*w1.x + a1.z*w2.x + a1.w*w3.x;
                acc1.y += a1.x*w0.y + a1.y*w1.y + a1.z*w2.y + a1.w*w3.y;
                acc1.z += a1.x*w0.z + a1.y*w1.z + a1.z*w2.z + a1.w*w3.z;
                acc1.w += a1.x*w0.w + a1.y*w1.w + a1.z*w2.w + a1.w*w3.w;
                acc2.x += a2.x*w0.x + a2.y*w1.x + a2.z*w2.x + a2.w*w3.x;
                acc2.y += a2.x*w0.y + a2.y*w1.y + a2.z*w2.y + a2.w*w3.y;
                acc2.z += a2.x*w0.z + a2.y*w1.z + a2.z*w2.z + a2.w*w3.z;
                acc2.w += a2.x*w0.w + a2.y*w1.w + a2.z*w2.w + a2.w*w3.w;
                acc3.x += a3.x*w0.x + a3.y*w1.x + a3.z*w2.x + a3.w*w3.x;
                acc3.y += a3.x*w0.y + a3.y*w1.y + a3.z*w2.y + a3.w*w3.y;
                acc3.z += a3.x*w0.z + a3.y*w1.z + a3.z*w2.z + a3.w*w3.z;
                acc3.w += a3.x*w0.w + a3.y*w1.w + a3.z*w2.w + a3.w*w3.w;
            }
            ((float4*)(h3s + (grp*4+0)*128))[fg] = acc0;
            ((float4*)(h3s + (grp*4+1)*128))[fg] = acc1;
            ((float4*)(h3s + (grp*4+2)*128))[fg] = acc2;
            ((float4*)(h3s + (grp*4+3)*128))[fg] = acc3;
        }
        __syncthreads();

        // ---- stage C: [32,128] @ [128,128] + bC -> relu -> + x -> out ----
        {
            float4 acc0 = biasC, acc1 = biasC, acc2 = biasC, acc3 = biasC;
            const float4* in0 = (const float4*)(h3s + (grp * 4 + 0) * 128);
            const float4* in1 = (const float4*)(h3s + (grp * 4 + 1) * 128);
            const float4* in2 = (const float4*)(h3s + (grp * 4 + 2) * 128);
            const float4* in3 = (const float4*)(h3s + (grp * 4 + 3) * 128);
            const float4* wv = (const float4*)wCs;
            #pragma unroll 4
            for (int i4 = 0; i4 < 32; i4++) {
                float4 w0 = wv[(i4*4+0)*32+fg], w1 = wv[(i4*4+1)*32+fg];
                float4 w2 = wv[(i4*4+2)*32+fg], w3 = wv[(i4*4+3)*32+fg];
                float4 a0 = in0[i4], a1 = in1[i4], a2 = in2[i4], a3 = in3[i4];
                acc0.x += a0.x*w0.x + a0.y*w1.x + a0.z*w2.x + a0.w*w3.x;
                acc0.y += a0.x*w0.y + a0.y*w1.y + a0.z*w2.y + a0.w*w3.y;
                acc0.z += a0.x*w0.z + a0.y*w1.z + a0.z*w2.z + a0.w*w3.z;
                acc0.w += a0.x*w0.w + a0.y*w1.w + a0.z*w2.w + a0.w*w3.w;
                acc1.x += a1.x*w0.x + a1.y*w1.x + a1.z*w2.x + a1.w*w3.x;
                acc1.y += a1.x*w0.y + a1.y*w1.y + a1.z*w2.y + a1.w*w3.y;
                acc1.z += a1.x*w0.z + a1.y*w1.z + a1.z*w2.z + a1.w*w3.z;
                acc1.w += a1.x*w0.w + a1.y*w1.w + a1.z*w2.w + a1.w*w3.w;
                acc2.x += a2.x*w0.x + a2.y*w1.x + a2.z*w2.x + a2.w*w3.x;
                acc2.y += a2.x*w0.y + a2.y*w1.y + a2.z*w2.y + a2.w*w3.y;
                acc2.z += a2.x*w0.z + a2.y*w1.z + a2.z*w2.z + a2.w*w3.z;
                acc2.w += a2.x*w0.w + a2.y*w1.w + a2.z*w2.w + a2.w*w3.w;
                acc3.x += a3.x*w0.x + a3.y*w1.x + a3.z*w2.x + a3.w*w3.x;
                acc3.y += a3.x*w0.y + a3.y*w1.y + a3.z*w2.y + a3.w*w3.y;
                acc3.z += a3.x*w0.z + a3.y*w1.z + a3.z*w2.z + a3.w*w3.z;
                acc3.w += a3.x*w0.w + a3.y*w1.w + a3.z*w2.w + a3.w*w3.w;
            }
            #pragma unroll
            for (int r = 0; r < 4; r++) {
                int node = node0 + grp * 4 + r;
                if (node >= n) continue;
                float4 acc = (r == 0) ? acc0 : (r == 1) ? acc1 : (r == 2) ? acc2 : acc3;
                float4 xv = ((const float4*)x)[(size_t)node * 32 + fg];
                float4 o;
                o.x = xv.x + fmaxf(acc.x, 0.f);
                o.y = xv.y + fmaxf(acc.y, 0.f);
                o.z = xv.z + fmaxf(acc.z, 0.f);
                o.w = xv.w + fmaxf(acc.w, 0.f);
                ((float4*)out)[(size_t)node * 32 + fg] = o;
            }
        }
    }
}

// ---------------- launcher --------------------------------------------------------
extern "C" void kernel_launch(void* const* d_in, const int* in_sizes, int n_in,
                              void* d_out, int out_size) {
    const float* x        = (const float*)d_in[0];
    const float* pos      = (const float*)d_in[1];
    const int*   ei       = (const int*)d_in[2];
    const float* mlp_w1   = (const float*)d_in[3];
    const float* mlp_b1   = (const float*)d_in[4];
    const float* mlp_w2   = (const float*)d_in[5];
    const float* mlp_b2   = (const float*)d_in[6];
    const float* conv1_w  = (const float*)d_in[7];
    const float* conv2_w  = (const float*)d_in[8];
    const float* conv2_b  = (const float*)d_in[9];
    const float* int_w    = (const float*)d_in[10];
    const float* int_b    = (const float*)d_in[11];
    const float* lin1_w   = (const float*)d_in[12];
    const float* lin1_b   = (const float*)d_in[13];
    float*       out      = (float*)d_out;

    int n = in_sizes[0] / DIMC;
    int E = in_sizes[2] / 2;
    if (n > MAXN) n = MAXN;

    {
        int total = n * 16;
        zero_agg_kernel<<<(total + 255) / 256, 256>>>(n);
        detect_dtype_kernel<<<1, 256>>>(ei, E, n);
    }

    build_table_kernel<<<512, 256>>>(mlp_w1, mlp_b1, mlp_w2, mlp_b2);

    cudaFuncSetAttribute(embed_kernel, cudaFuncAttributeMaxDynamicSharedMemorySize,
                         EMBED_SMEM_BYTES);
    embed_kernel<<<444, 256, EMBED_SMEM_BYTES>>>(x, conv1_w, n);

    // 2 edges per warp, 8 warps per block -> 16 edges per block
    unsigned int eblocks = (unsigned int)((E + 15) / 16);
    edge_kernel<<<eblocks, 256>>>(ei, pos, E, n);

    static_assert(TAIL_SMEM_BYTES <= 224 * 1024, "tail smem too large");
    cudaFuncSetAttribute(tail_kernel, cudaFuncAttributeMaxDynamicSharedMemorySize,
                         TAIL_SMEM_BYTES);
    tail_kernel<<<148, 256, TAIL_SMEM_BYTES>>>(x, conv2_w, conv2_b, int_w, int_b,
                                               lin1_w, lin1_b, out, n);
}

// round 7
// speedup vs baseline: 1.3680x; 1.0312x over previous
#include <cuda_runtime.h>
#include <cuda_bf16.h>
#include <math.h>

#define DIMC   128
#define NF     64
#define NG     50
#define NBINS  32768
#define DMAXF  16.0f
#define MAXN   100352
#define LOG2C  0.69314718055994531f
#define CUTOFFF 10.0f

// ---------------- scratch (static device arrays; no runtime alloc) ----------------
__device__ uint4  g_hbf [(size_t)MAXN * 8];     // bf16 h = x @ conv_lin1_w [N,64]
__device__ uint4  g_tbf [(size_t)NBINS * 8];    // bf16 W(d)*C(d) table [NBINS,64]
__device__ float4 g_agg4[(size_t)MAXN * 16];    // fp32 segment-summed messages [N,64]
__device__ int    g_is64;

__device__ __forceinline__ float sspf(float v) {
    return fmaxf(v, 0.0f) + log1pf(__expf(-fabsf(v))) - LOG2C;
}

// ---------------- kernel 0a: zero the aggregation buffer --------------------------
__global__ void zero_agg_kernel(int n) {
    int total = n * 16;
    int idx = blockIdx.x * blockDim.x + threadIdx.x;
    if (idx < total)
        g_agg4[idx] = make_float4(0.f, 0.f, 0.f, 0.f);
}

// ---------------- kernel 0b: detect edge_index dtype ------------------------------
__global__ void detect_dtype_kernel(const int* __restrict__ ei, int E, int n) {
    __shared__ int bad;
    if (threadIdx.x == 0) bad = 0;
    __syncthreads();
    for (int i = threadIdx.x; i < 1024; i += blockDim.x) {
        long long e = ((long long)i * (long long)E) / 1024LL;
        int lo = ei[2 * e];
        int hi = ei[2 * e + 1];
        if (hi != 0 || lo < 0 || lo >= n) atomicExch(&bad, 1);
    }
    __syncthreads();
    if (threadIdx.x == 0) g_is64 = bad ? 0 : 1;
}

// ---------------- kernel 1: build W(d)*C(d) table (bf16 output) -------------------
__global__ void build_table_kernel(const float* __restrict__ w1, const float* __restrict__ b1,
                                   const float* __restrict__ w2, const float* __restrict__ b2) {
    __shared__ float w1s[NG * NF];
    __shared__ float w2s[NF * NF];
    __shared__ float b1s[NF], b2s[NF];
    __shared__ float attr[4][NG];
    __shared__ float f1s [4][NF];

    int tid = threadIdx.x;
    for (int i = tid; i < NG * NF; i += 256) w1s[i] = w1[i];
    for (int i = tid; i < NF * NF; i += 256) w2s[i] = w2[i];
    if (tid < NF) { b1s[tid] = b1[tid]; b2s[tid] = b2[tid]; }
    __syncthreads();

    const int grp = tid >> 6;
    const int f   = tid & 63;
    const float delta    = DMAXF / (float)(NBINS - 1);
    const float off_step = CUTOFFF / (float)(NG - 1);
    const float coeff    = -0.5f / (off_step * off_step);
    __nv_bfloat16* tab = (__nv_bfloat16*)g_tbf;

    for (int base = blockIdx.x * 4; base < NBINS; base += gridDim.x * 4) {
        int bin = base + grp;
        float d = (float)bin * delta;

        if (f < NG) {
            float t = d - (float)f * off_step;
            attr[grp][f] = __expf(coeff * t * t);
        }
        __syncthreads();

        float z = b1s[f];
        #pragma unroll
        for (int g = 0; g < NG; g++) z += attr[grp][g] * w1s[g * NF + f];
        f1s[grp][f] = sspf(z);
        __syncthreads();

        float wv = b2s[f];
        #pragma unroll
        for (int i = 0; i < NF; i++) wv += f1s[grp][i] * w2s[i * NF + f];

        float C = 0.5f * (cosf(d * 0.31415926535897932f) + 1.0f);
        tab[(size_t)bin * NF + f] = __float2bfloat16(wv * C);
        __syncthreads();
    }
}

// ---------------- kernel 2: node embed h = x @ conv_lin1_w  [N,64] (bf16 out) -----
#define ETILE 64
#define EMBED_SMEM_BYTES ((DIMC * 16 + ETILE * 32) * 16)

__global__ void embed_kernel(const float* __restrict__ x, const float* __restrict__ w, int n) {
    extern __shared__ float4 esm[];
    float4* ws = esm;
    float4* xs = esm + DIMC * 16;

    int tid = threadIdx.x;
    for (int i = tid; i < DIMC * 16; i += 256) ws[i] = ((const float4*)w)[i];

    const int fg = tid & 15;
    const int nr = tid >> 4;
    const int ntiles = (n + ETILE - 1) / ETILE;
    uint2* hb = (uint2*)g_hbf;          // row = 16 uint2 (64 bf16)

    for (int tile = blockIdx.x; tile < ntiles; tile += gridDim.x) {
        int node0 = tile * ETILE;
        __syncthreads();
        for (int i = tid; i < ETILE * 32; i += 256) {
            int node = node0 + (i >> 5);
            xs[i] = (node < n) ? ((const float4*)x)[(size_t)node * 32 + (i & 31)]
                               : make_float4(0.f, 0.f, 0.f, 0.f);
        }
        __syncthreads();

        float4 acc0 = make_float4(0.f,0.f,0.f,0.f), acc1 = acc0, acc2 = acc0, acc3 = acc0;
        const float4* xr0 = xs + (nr * 4 + 0) * 32;
        const float4* xr1 = xs + (nr * 4 + 1) * 32;
        const float4* xr2 = xs + (nr * 4 + 2) * 32;
        const float4* xr3 = xs + (nr * 4 + 3) * 32;

        #pragma unroll 4
        for (int k4 = 0; k4 < 32; k4++) {
            float4 w0 = ws[(k4 * 4 + 0) * 16 + fg];
            float4 w1 = ws[(k4 * 4 + 1) * 16 + fg];
            float4 w2 = ws[(k4 * 4 + 2) * 16 + fg];
            float4 w3 = ws[(k4 * 4 + 3) * 16 + fg];
            float4 a0 = xr0[k4], a1 = xr1[k4], a2 = xr2[k4], a3 = xr3[k4];

            acc0.x += a0.x*w0.x + a0.y*w1.x + a0.z*w2.x + a0.w*w3.x;
            acc0.y += a0.x*w0.y + a0.y*w1.y + a0.z*w2.y + a0.w*w3.y;
            acc0.z += a0.x*w0.z + a0.y*w1.z + a0.z*w2.z + a0.w*w3.z;
            acc0.w += a0.x*w0.w + a0.y*w1.w + a0.z*w2.w + a0.w*w3.w;

            acc1.x += a1.x*w0.x + a1.y*w1.x + a1.z*w2.x + a1.w*w3.x;
            acc1.y += a1.x*w0.y + a1.y*w1.y + a1.z*w2.y + a1.w*w3.y;
            acc1.z += a1.x*w0.z + a1.y*w1.z + a1.z*w2.z + a1.w*w3.z;
            acc1.w += a1.x*w0.w + a1.y*w1.w + a1.z*w2.w + a1.w*w3.w;

            acc2.x += a2.x*w0.x + a2.y*w1.x + a2.z*w2.x + a2.w*w3.x;
            acc2.y += a2.x*w0.y + a2.y*w1.y + a2.z*w2.y + a2.w*w3.y;
            acc2.z += a2.x*w0.z + a2.y*w1.z + a2.z*w2.z + a2.w*w3.z;
            acc2.w += a2.x*w0.w + a2.y*w1.w + a2.z*w2.w + a2.w*w3.w;

            acc3.x += a3.x*w0.x + a3.y*w1.x + a3.z*w2.x + a3.w*w3.x;
            acc3.y += a3.x*w0.y + a3.y*w1.y + a3.z*w2.y + a3.w*w3.y;
            acc3.z += a3.x*w0.z + a3.y*w1.z + a3.z*w2.z + a3.w*w3.z;
            acc3.w += a3.x*w0.w + a3.y*w1.w + a3.z*w2.w + a3.w*w3.w;
        }

        #pragma unroll
        for (int r = 0; r < 4; r++) {
            int node = node0 + nr * 4 + r;
            if (node >= n) continue;
            float4 a = (r == 0) ? acc0 : (r == 1) ? acc1 : (r == 2) ? acc2 : acc3;
            __nv_bfloat162 p0 = __floats2bfloat162_rn(a.x, a.y);
            __nv_bfloat162 p1 = __floats2bfloat162_rn(a.z, a.w);
            uint2 v;
            v.x = *reinterpret_cast<unsigned*>(&p0);
            v.y = *reinterpret_cast<unsigned*>(&p1);
            hb[(size_t)node * 16 + fg] = v;
        }
    }
}

// ---------------- kernel 3: per-edge message + scatter ----------------------------
// 8 threads/edge (4 edges/warp). Lane sub==0 loads idx/pos, computes nearest bin;
// broadcast via shfl width 8. bf16 table row + bf16 h row (1 LDG.128 each per
// thread = 8 values), fp32 accumulate via 2x red.global.add.v4.f32.
__global__ void edge_kernel(const int* __restrict__ ei,
                            const float* __restrict__ pos, int E, int n) {
    int lane = threadIdx.x & 31;
    int sub  = lane & 7;
    long long t = (long long)blockIdx.x * blockDim.x + threadIdx.x;
    long long e = t >> 3;
    bool valid = (e < (long long)E);

    int src = 0, dst = 0, bin = 0;
    if (sub == 0 && valid) {
        if (g_is64) { src = ei[2 * (size_t)e]; dst = ei[2 * ((size_t)E + e)]; }
        else        { src = ei[(size_t)e];     dst = ei[(size_t)E + e];       }
        src = min(max(src, 0), n - 1);
        dst = min(max(dst, 0), n - 1);
        float dx = pos[dst * 3 + 0] - pos[src * 3 + 0];
        float dy = pos[dst * 3 + 1] - pos[src * 3 + 1];
        float dz = pos[dst * 3 + 2] - pos[src * 3 + 2];
        float d  = sqrtf(dx * dx + dy * dy + dz * dz);
        float u = d * ((float)(NBINS - 1) / DMAXF);
        bin = __float2int_rn(u);
        if (bin > NBINS - 1) bin = NBINS - 1;
    }
    src = __shfl_sync(0xffffffffu, src, 0, 8);
    dst = __shfl_sync(0xffffffffu, dst, 0, 8);
    bin = __shfl_sync(0xffffffffu, bin, 0, 8);
    if (!valid) return;

    uint4 tw = g_tbf[(size_t)bin * 8 + sub];
    uint4 th = g_hbf[(size_t)src * 8 + sub];
    const __nv_bfloat162* wp = (const __nv_bfloat162*)&tw;
    const __nv_bfloat162* hp = (const __nv_bfloat162*)&th;

    float2 w0 = __bfloat1622float2(wp[0]), h0 = __bfloat1622float2(hp[0]);
    float2 w1 = __bfloat1622float2(wp[1]), h1 = __bfloat1622float2(hp[1]);
    float2 w2 = __bfloat1622float2(wp[2]), h2 = __bfloat1622float2(hp[2]);
    float2 w3 = __bfloat1622float2(wp[3]), h3 = __bfloat1622float2(hp[3]);

    float m0x = w0.x * h0.x, m0y = w0.y * h0.y, m0z = w1.x * h1.x, m0w = w1.y * h1.y;
    float m1x = w2.x * h2.x, m1y = w2.y * h2.y, m1z = w3.x * h3.x, m1w = w3.y * h3.y;

    float4* dstp = g_agg4 + (size_t)dst * 16 + sub * 2;
    asm volatile("{ .reg .u64 ga; cvta.to.global.u64 ga, %0; "
                 "red.global.add.v4.f32 [ga], {%1, %2, %3, %4}; }"
                 :: "l"(dstp), "f"(m0x), "f"(m0y), "f"(m0z), "f"(m0w) : "memory");
    asm volatile("{ .reg .u64 ga; cvta.to.global.u64 ga, %0; "
                 "red.global.add.v4.f32 [ga], {%1, %2, %3, %4}; }"
                 :: "l"(dstp + 1), "f"(m1x), "f"(m1y), "f"(m1z), "f"(m1w) : "memory");
}

// ---------------- kernel 4: fused node tail (unchanged, fp32, at scalar floor) ----
#define TAIL_SMEM_FLOATS (8192 + 16384 + 16384 + 2048 + 4096 + 4096)
#define TAIL_SMEM_BYTES  (TAIL_SMEM_FLOATS * 4)

__global__ void tail_kernel(const float* __restrict__ x,
                            const float* __restrict__ wA, const float* __restrict__ bA,
                            const float* __restrict__ wB, const float* __restrict__ bB,
                            const float* __restrict__ wC, const float* __restrict__ bC,
                            float* __restrict__ out, int n) {
    extern __shared__ float sm[];
    float* wAs   = sm;
    float* wBs   = wAs + 8192;
    float* wCs   = wBs + 16384;
    float* aggs  = wCs + 16384;
    float* h2s   = aggs + 2048;
    float* h3s   = h2s + 4096;

    int tid = threadIdx.x;
    for (int i = tid; i < 8192;  i += 256) wAs[i] = wA[i];
    for (int i = tid; i < 16384; i += 256) { wBs[i] = wB[i]; wCs[i] = wC[i]; }

    const int fg  = tid & 31;
    const int grp = tid >> 5;
    const int ntiles = (n + 31) >> 5;
    const float4 biasA = make_float4(bA[fg*4+0], bA[fg*4+1], bA[fg*4+2], bA[fg*4+3]);
    const float4 biasB = make_float4(bB[fg*4+0], bB[fg*4+1], bB[fg*4+2], bB[fg*4+3]);
    const float4 biasC = make_float4(bC[fg*4+0], bC[fg*4+1], bC[fg*4+2], bC[fg*4+3]);

    for (int tile = blockIdx.x; tile < ntiles; tile += gridDim.x) {
        int node0 = tile << 5;
        __syncthreads();
        for (int i = tid; i < 512; i += 256) {
            int r = i >> 4, c = i & 15;
            int node = node0 + r;
            float4 v = (node < n) ? g_agg4[(size_t)node * 16 + c]
                                  : make_float4(0.f, 0.f, 0.f, 0.f);
            ((float4*)(aggs + r * 64))[c] = v;
        }
        __syncthreads();

        {
            float4 acc0 = biasA, acc1 = biasA, acc2 = biasA, acc3 = biasA;
            const float4* in0 = (const float4*)(aggs + (grp * 4 + 0) * 64);
            const float4* in1 = (const float4*)(aggs + (grp * 4 + 1) * 64);
            const float4* in2 = (const float4*)(aggs + (grp * 4 + 2) * 64);
            const float4* in3 = (const float4*)(aggs + (grp * 4 + 3) * 64);
            const float4* wv = (const float4*)wAs;
            #pragma unroll 4
            for (int i4 = 0; i4 < 16; i4++) {
                float4 w0 = wv[(i4*4+0)*32+fg], w1 = wv[(i4*4+1)*32+fg];
                float4 w2 = wv[(i4*4+2)*32+fg], w3 = wv[(i4*4+3)*32+fg];
                float4 a0 = in0[i4], a1 = in1[i4], a2 = in2[i4], a3 = in3[i4];
                acc0.x += a0.x*w0.x + a0.y*w1.x + a0.z*w2.x + a0.w*w3.x;
                acc0.y += a0.x*w0.y + a0.y*w1.y + a0.z*w2.y + a0.w*w3.y;
                acc0.z += a0.x*w0.z + a0.y*w1.z + a0.z*w2.z + a0.w*w3.z;
                acc0.w += a0.x*w0.w + a0.y*w1.w + a0.z*w2.w + a0.w*w3.w;
                acc1.x += a1.x*w0.x + a1.y*w1.x + a1.z*w2.x + a1.w*w3.x;
                acc1.y += a1.x*w0.y + a1.y*w1.y + a1.z*w2.y + a1.w*w3.y;
                acc1.z += a1.x*w0.z + a1.y*w1.z + a1.z*w2.z + a1.w*w3.z;
                acc1.w += a1.x*w0.w + a1.y*w1.w + a1.z*w2.w + a1.w*w3.w;
                acc2.x += a2.x*w0.x + a2.y*w1.x + a2.z*w2.x + a2.w*w3.x;
                acc2.y += a2.x*w0.y + a2.y*w1.y + a2.z*w2.y + a2.w*w3.y;
                acc2.z += a2.x*w0.z + a2.y*w1.z + a2.z*w2.z + a2.w*w3.z;
                acc2.w += a2.x*w0.w + a2.y*w1.w + a2.z*w2.w + a2.w*w3.w;
                acc3.x += a3.x*w0.x + a3.y*w1.x + a3.z*w2.x + a3.w*w3.x;
                acc3.y += a3.x*w0.y + a3.y*w1.y + a3.z*w2.y + a3.w*w3.y;
                acc3.z += a3.x*w0.z + a3.y*w1.z + a3.z*w2.z + a3.w*w3.z;
                acc3.w += a3.x*w0.w + a3.y*w1.w + a3.z*w2.w + a3.w*w3.w;
            }
            ((float4*)(h2s + (grp*4+0)*128))[fg] = make_float4(sspf(acc0.x), sspf(acc0.y), sspf(acc0.z), sspf(acc0.w));
            ((float4*)(h2s + (grp*4+1)*128))[fg] = make_float4(sspf(acc1.x), sspf(acc1.y), sspf(acc1.z), sspf(acc1.w));
            ((float4*)(h2s + (grp*4+2)*128))[fg] = make_float4(sspf(acc2.x), sspf(acc2.y), sspf(acc2.z), sspf(acc2.w));
            ((float4*)(h2s + (grp*4+3)*128))[fg] = make_float4(sspf(acc3.x), sspf(acc3.y), sspf(acc3.z), sspf(acc3.w));
        }
        __syncthreads();

        {
            float4 acc0 = biasB, acc1 = biasB, acc2 = biasB, acc3 = biasB;
            const float4* in0 = (const float4*)(h2s + (grp * 4 + 0) * 128);
            const float4* in1 = (const float4*)(h2s + (grp * 4 + 1) * 128);
            const float4* in2 = (const float4*)(h2s + (grp * 4 + 2) * 128);
            const float4* in3 = (const float4*)(h2s + (grp * 4 + 3) * 128);
            const float4* wv = (const float4*)wBs;
            #pragma unroll 4
            for (int i4 = 0; i4 < 32; i4++) {
                float4 w0 = wv[(i4*4+0)*32+fg], w1 = wv[(i4*4+1)*32+fg];
                float4 w2 = wv[(i4*4+2)*32+fg], w3 = wv[(i4*4+3)*32+fg];
                float4 a0 = in0[i4], a1 = in1[i4], a2 = in2[i4], a3 = in3[i4];
                acc0.x += a0.x*w0.x + a0.y*w1.x + a0.z*w2.x + a0.w*w3.x;
                acc0.y += a0.x*w0.y + a0.y*w1.y + a0.z*w2.y + a0.w*w3.y;
                acc0.z += a0.x*w0.z + a0.y*w1.z + a0.z*w2.z + a0.w*w3.z;
                acc0.w += a0.x*w0.w + a0.y*w1.w + a0.z*w2.w + a0.w*w3.w;
                acc1.x += a1.x*w0.x + a1.y*w1.x + a1.z*w2.x + a1.w*w3.x;
                acc1.y += a1.x*w0.y + a1.y*w1.y + a1.z*w2.y + a1.w*w3.y;
                acc1.z += a1.x*w0.z + a1.y*w1.z + a1.z*w2.z + a1.w*w3.z;
                acc1.w += a1.x*w0.w + a1.y*w1.w + a1.z*w2.w + a1.w*w3.w;
                acc2.x += a2.x*w0.x + a2.y*w1.x + a2.z*w2.x + a2.w*w3.x;
                acc2.y += a2.x*w0.y + a2.y*w1.y + a2.z*w2.y + a2.w*w3.y;
                acc2.z += a2.x*w0.z + a2.y*w1.z + a2.z*w2.z + a2.w*w3.z;
                acc2.w += a2.x*w0.w + a2.y*w1.w + a2.z*w2.w + a2.w*w3.w;
                acc3.x += a3.x*w0.x + a3.y*w1.x + a3.z*w2.x + a3.w*w3.x;
                acc3.y += a3.x*w0.y + a3.y*w1.y + a3.z*w2.y + a3.w*w3.y;
                acc3.z += a3.x*w0.z + a3.y*w1.z + a3.z*w2.z + a3.w*w3.z;
                acc3.w += a3.x*w0.w + a3.y*w1.w + a3.z*w2.w + a3.w*w3.w;
            }
            ((float4*)(h3s + (grp*4+0)*128))[fg] = acc0;
            ((float4*)(h3s + (grp*4+1)*128))[fg] = acc1;
            ((float4*)(h3s + (grp*4+2)*128))[fg] = acc2;
            ((float4*)(h3s + (grp*4+3)*128))[fg] = acc3;
        }
        __syncthreads();

        {
            float4 acc0 = biasC, acc1 = biasC, acc2 = biasC, acc3 = biasC;
            const float4* in0 = (const float4*)(h3s + (grp * 4 + 0) * 128);
            const float4* in1 = (const float4*)(h3s + (grp * 4 + 1) * 128);
            const float4* in2 = (const float4*)(h3s + (grp * 4 + 2) * 128);
            const float4* in3 = (const float4*)(h3s + (grp * 4 + 3) * 128);
            const float4* wv = (const float4*)wCs;
            #pragma unroll 4
            for (int i4 = 0; i4 < 32; i4++) {
                float4 w0 = wv[(i4*4+0)*32+fg], w1 = wv[(i4*4+1)*32+fg];
                float4 w2 = wv[(i4*4+2)*32+fg], w3 = wv[(i4*4+3)*32+fg];
                float4 a0 = in0[i4], a1 = in1[i4], a2 = in2[i4], a3 = in3[i4];
                acc0.x += a0.x*w0.x + a0.y*w1.x + a0.z*w2.x + a0.w*w3.x;
                acc0.y += a0.x*w0.y + a0.y*w1.y + a0.z*w2.y + a0.w*w3.y;
                acc0.z += a0.x*w0.z + a0.y*w1.z + a0.z*w2.z + a0.w*w3.z;
                acc0.w += a0.x*w0.w + a0.y*w1.w + a0.z*w2.w + a0.w*w3.w;
                acc1.x += a1.x*w0.x + a1.y*w1.x + a1.z*w2.x + a1.w*w3.x;
                acc1.y += a1.x*w0.y + a1.y*w1.y + a1.z*w2.y + a1.w*w3.y;
                acc1.z += a1.x*w0.z + a1.y*w1.z + a1.z*w2.z + a1.w*w3.z;
                acc1.w += a1.x*w0.w + a1.y*w1.w + a1.z*w2.w + a1.w*w3.w;
                acc2.x += a2.x*w0.x + a2.y*w1.x + a2.z*w2.x + a2.w*w3.x;
                acc2.y += a2.x*w0.y + a2.y*w1.y + a2.z*w2.y + a2.w*w3.y;
                acc2.z += a2.x*w0.z + a2.y*w1.z + a2.z*w2.z + a2.w*w3.z;
                acc2.w += a2.x*w0.w + a2.y*w1.w + a2.z*w2.w + a2.w*w3.w;
                acc3.x += a3.x*w0.x + a3.y*w1.x + a3.z*w2.x + a3.w*w3.x;
                acc3.y += a3.x*w0.y + a3.y*w1.y + a3.z*w2.y + a3.w*w3.y;
                acc3.z += a3.x*w0.z + a3.y*w1.z + a3.z*w2.z + a3.w*w3.z;
                acc3.w += a3.x*w0.w + a3.y*w1.w + a3.z*w2.w + a3.w*w3.w;
            }
            #pragma unroll
            for (int r = 0; r < 4; r++) {
                int node = node0 + grp * 4 + r;
                if (node >= n) continue;
                float4 acc = (r == 0) ? acc0 : (r == 1) ? acc1 : (r == 2) ? acc2 : acc3;
                float4 xv = ((const float4*)x)[(size_t)node * 32 + fg];
                float4 o;
                o.x = xv.x + fmaxf(acc.x, 0.f);
                o.y = xv.y + fmaxf(acc.y, 0.f);
                o.z = xv.z + fmaxf(acc.z, 0.f);
                o.w = xv.w + fmaxf(acc.w, 0.f);
                ((float4*)out)[(size_t)node * 32 + fg] = o;
            }
        }
    }
}

// ---------------- launcher --------------------------------------------------------
extern "C" void kernel_launch(void* const* d_in, const int* in_sizes, int n_in,
                              void* d_out, int out_size) {
    const float* x        = (const float*)d_in[0];
    const float* pos      = (const float*)d_in[1];
    const int*   ei       = (const int*)d_in[2];
    const float* mlp_w1   = (const float*)d_in[3];
    const float* mlp_b1   = (const float*)d_in[4];
    const float* mlp_w2   = (const float*)d_in[5];
    const float* mlp_b2   = (const float*)d_in[6];
    const float* conv1_w  = (const float*)d_in[7];
    const float* conv2_w  = (const float*)d_in[8];
    const float* conv2_b  = (const float*)d_in[9];
    const float* int_w    = (const float*)d_in[10];
    const float* int_b    = (const float*)d_in[11];
    const float* lin1_w   = (const float*)d_in[12];
    const float* lin1_b   = (const float*)d_in[13];
    float*       out      = (float*)d_out;

    int n = in_sizes[0] / DIMC;
    int E = in_sizes[2] / 2;
    if (n > MAXN) n = MAXN;

    {
        int total = n * 16;
        zero_agg_kernel<<<(total + 255) / 256, 256>>>(n);
        detect_dtype_kernel<<<1, 256>>>(ei, E, n);
    }

    build_table_kernel<<<512, 256>>>(mlp_w1, mlp_b1, mlp_w2, mlp_b2);

    cudaFuncSetAttribute(embed_kernel, cudaFuncAttributeMaxDynamicSharedMemorySize,
                         EMBED_SMEM_BYTES);
    embed_kernel<<<444, 256, EMBED_SMEM_BYTES>>>(x, conv1_w, n);

    // 8 threads per edge -> 32 edges per 256-thread block
    {
        unsigned long long ethreads = (unsigned long long)E * 8ULL;
        unsigned int eblocks = (unsigned int)((ethreads + 255ULL) / 256ULL);
        edge_kernel<<<eblocks, 256>>>(ei, pos, E, n);
    }

    static_assert(TAIL_SMEM_BYTES <= 224 * 1024, "tail smem too large");
    cudaFuncSetAttribute(tail_kernel, cudaFuncAttributeMaxDynamicSharedMemorySize,
                         TAIL_SMEM_BYTES);
    tail_kernel<<<148, 256, TAIL_SMEM_BYTES>>>(x, conv2_w, conv2_b, int_w, int_b,
                                               lin1_w, lin1_b, out, n);
}

// round 8
// speedup vs baseline: 1.5212x; 1.1120x over previous
#include <cuda_runtime.h>
#include <cuda_bf16.h>
#include <math.h>

#define DIMC   128
#define NF     64
#define NG     50
#define NBINS  32768
#define DMAXF  16.0f
#define MAXN   100352
#define LOG2C  0.69314718055994531f
#define CUTOFFF 10.0f

// ---------------- scratch (static device arrays; no runtime alloc) ----------------
__device__ uint4  g_hbf [(size_t)MAXN * 8];     // bf16 h = x @ conv_lin1_w [N,64]
__device__ uint4  g_tbf [(size_t)NBINS * 8];    // bf16 W(d)*C(d) table [NBINS,64]
__device__ uint4  g_aggbf[(size_t)MAXN * 8];    // bf16 segment-summed messages [N,64]
__device__ int    g_is64;

__device__ __forceinline__ float sspf(float v) {
    return fmaxf(v, 0.0f) + log1pf(__expf(-fabsf(v))) - LOG2C;
}

// ---------------- kernel 0a: zero the aggregation buffer --------------------------
__global__ void zero_agg_kernel(int n) {
    int total = n * 8;
    int idx = blockIdx.x * blockDim.x + threadIdx.x;
    if (idx < total)
        g_aggbf[idx] = make_uint4(0u, 0u, 0u, 0u);
}

// ---------------- kernel 0b: detect edge_index dtype ------------------------------
__global__ void detect_dtype_kernel(const int* __restrict__ ei, int E, int n) {
    __shared__ int bad;
    if (threadIdx.x == 0) bad = 0;
    __syncthreads();
    for (int i = threadIdx.x; i < 1024; i += blockDim.x) {
        long long e = ((long long)i * (long long)E) / 1024LL;
        int lo = ei[2 * e];
        int hi = ei[2 * e + 1];
        if (hi != 0 || lo < 0 || lo >= n) atomicExch(&bad, 1);
    }
    __syncthreads();
    if (threadIdx.x == 0) g_is64 = bad ? 0 : 1;
}

// ---------------- kernel 1: build W(d)*C(d) table (bf16 output) -------------------
__global__ void build_table_kernel(const float* __restrict__ w1, const float* __restrict__ b1,
                                   const float* __restrict__ w2, const float* __restrict__ b2) {
    __shared__ float w1s[NG * NF];
    __shared__ float w2s[NF * NF];
    __shared__ float b1s[NF], b2s[NF];
    __shared__ float attr[4][NG];
    __shared__ float f1s [4][NF];

    int tid = threadIdx.x;
    for (int i = tid; i < NG * NF; i += 256) w1s[i] = w1[i];
    for (int i = tid; i < NF * NF; i += 256) w2s[i] = w2[i];
    if (tid < NF) { b1s[tid] = b1[tid]; b2s[tid] = b2[tid]; }
    __syncthreads();

    const int grp = tid >> 6;
    const int f   = tid & 63;
    const float delta    = DMAXF / (float)(NBINS - 1);
    const float off_step = CUTOFFF / (float)(NG - 1);
    const float coeff    = -0.5f / (off_step * off_step);
    __nv_bfloat16* tab = (__nv_bfloat16*)g_tbf;

    for (int base = blockIdx.x * 4; base < NBINS; base += gridDim.x * 4) {
        int bin = base + grp;
        float d = (float)bin * delta;

        if (f < NG) {
            float t = d - (float)f * off_step;
            attr[grp][f] = __expf(coeff * t * t);
        }
        __syncthreads();

        float z = b1s[f];
        #pragma unroll
        for (int g = 0; g < NG; g++) z += attr[grp][g] * w1s[g * NF + f];
        f1s[grp][f] = sspf(z);
        __syncthreads();

        float wv = b2s[f];
        #pragma unroll
        for (int i = 0; i < NF; i++) wv += f1s[grp][i] * w2s[i * NF + f];

        float C = 0.5f * (cosf(d * 0.31415926535897932f) + 1.0f);
        tab[(size_t)bin * NF + f] = __float2bfloat16(wv * C);
        __syncthreads();
    }
}

// ---------------- kernel 2: node embed h = x @ conv_lin1_w  [N,64] (bf16 out) -----
#define ETILE 64
#define EMBED_SMEM_BYTES ((DIMC * 16 + ETILE * 32) * 16)

__global__ void embed_kernel(const float* __restrict__ x, const float* __restrict__ w, int n) {
    extern __shared__ float4 esm[];
    float4* ws = esm;
    float4* xs = esm + DIMC * 16;

    int tid = threadIdx.x;
    for (int i = tid; i < DIMC * 16; i += 256) ws[i] = ((const float4*)w)[i];

    const int fg = tid & 15;
    const int nr = tid >> 4;
    const int ntiles = (n + ETILE - 1) / ETILE;
    uint2* hb = (uint2*)g_hbf;          // row = 16 uint2 (64 bf16)

    for (int tile = blockIdx.x; tile < ntiles; tile += gridDim.x) {
        int node0 = tile * ETILE;
        __syncthreads();
        for (int i = tid; i < ETILE * 32; i += 256) {
            int node = node0 + (i >> 5);
            xs[i] = (node < n) ? ((const float4*)x)[(size_t)node * 32 + (i & 31)]
                               : make_float4(0.f, 0.f, 0.f, 0.f);
        }
        __syncthreads();

        float4 acc0 = make_float4(0.f,0.f,0.f,0.f), acc1 = acc0, acc2 = acc0, acc3 = acc0;
        const float4* xr0 = xs + (nr * 4 + 0) * 32;
        const float4* xr1 = xs + (nr * 4 + 1) * 32;
        const float4* xr2 = xs + (nr * 4 + 2) * 32;
        const float4* xr3 = xs + (nr * 4 + 3) * 32;

        #pragma unroll 4
        for (int k4 = 0; k4 < 32; k4++) {
            float4 w0 = ws[(k4 * 4 + 0) * 16 + fg];
            float4 w1 = ws[(k4 * 4 + 1) * 16 + fg];
            float4 w2 = ws[(k4 * 4 + 2) * 16 + fg];
            float4 w3 = ws[(k4 * 4 + 3) * 16 + fg];
            float4 a0 = xr0[k4], a1 = xr1[k4], a2 = xr2[k4], a3 = xr3[k4];

            acc0.x += a0.x*w0.x + a0.y*w1.x + a0.z*w2.x + a0.w*w3.x;
            acc0.y += a0.x*w0.y + a0.y*w1.y + a0.z*w2.y + a0.w*w3.y;
            acc0.z += a0.x*w0.z + a0.y*w1.z + a0.z*w2.z + a0.w*w3.z;
            acc0.w += a0.x*w0.w + a0.y*w1.w + a0.z*w2.w + a0.w*w3.w;

            acc1.x += a1.x*w0.x + a1.y*w1.x + a1.z*w2.x + a1.w*w3.x;
            acc1.y += a1.x*w0.y + a1.y*w1.y + a1.z*w2.y + a1.w*w3.y;
            acc1.z += a1.x*w0.z + a1.y*w1.z + a1.z*w2.z + a1.w*w3.z;
            acc1.w += a1.x*w0.w + a1.y*w1.w + a1.z*w2.w + a1.w*w3.w;

            acc2.x += a2.x*w0.x + a2.y*w1.x + a2.z*w2.x + a2.w*w3.x;
            acc2.y += a2.x*w0.y + a2.y*w1.y + a2.z*w2.y + a2.w*w3.y;
            acc2.z += a2.x*w0.z + a2.y*w1.z + a2.z*w2.z + a2.w*w3.z;
            acc2.w += a2.x*w0.w + a2.y*w1.w + a2.z*w2.w + a2.w*w3.w;

            acc3.x += a3.x*w0.x + a3.y*w1.x + a3.z*w2.x + a3.w*w3.x;
            acc3.y += a3.x*w0.y + a3.y*w1.y + a3.z*w2.y + a3.w*w3.y;
            acc3.z += a3.x*w0.z + a3.y*w1.z + a3.z*w2.z + a3.w*w3.z;
            acc3.w += a3.x*w0.w + a3.y*w1.w + a3.z*w2.w + a3.w*w3.w;
        }

        #pragma unroll
        for (int r = 0; r < 4; r++) {
            int node = node0 + nr * 4 + r;
            if (node >= n) continue;
            float4 a = (r == 0) ? acc0 : (r == 1) ? acc1 : (r == 2) ? acc2 : acc3;
            __nv_bfloat162 p0 = __floats2bfloat162_rn(a.x, a.y);
            __nv_bfloat162 p1 = __floats2bfloat162_rn(a.z, a.w);
            uint2 v;
            v.x = *reinterpret_cast<unsigned*>(&p0);
            v.y = *reinterpret_cast<unsigned*>(&p1);
            hb[(size_t)node * 16 + fg] = v;
        }
    }
}

// ---------------- kernel 3: per-edge message + scatter ----------------------------
// 8 threads/edge. bf16 table row * bf16 h row (hmul2), scatter via ONE
// red.global.add.noftz.v4.bf16x2 (8 bf16 adds in a single 16B reduction).
__global__ void edge_kernel(const int* __restrict__ ei,
                            const float* __restrict__ pos, int E, int n) {
    int lane = threadIdx.x & 31;
    int sub  = lane & 7;
    long long t = (long long)blockIdx.x * blockDim.x + threadIdx.x;
    long long e = t >> 3;
    bool valid = (e < (long long)E);

    int src = 0, dst = 0, bin = 0;
    if (sub == 0 && valid) {
        if (g_is64) { src = ei[2 * (size_t)e]; dst = ei[2 * ((size_t)E + e)]; }
        else        { src = ei[(size_t)e];     dst = ei[(size_t)E + e];       }
        src = min(max(src, 0), n - 1);
        dst = min(max(dst, 0), n - 1);
        float dx = pos[dst * 3 + 0] - pos[src * 3 + 0];
        float dy = pos[dst * 3 + 1] - pos[src * 3 + 1];
        float dz = pos[dst * 3 + 2] - pos[src * 3 + 2];
        float d  = sqrtf(dx * dx + dy * dy + dz * dz);
        float u = d * ((float)(NBINS - 1) / DMAXF);
        bin = __float2int_rn(u);
        if (bin > NBINS - 1) bin = NBINS - 1;
    }
    src = __shfl_sync(0xffffffffu, src, 0, 8);
    dst = __shfl_sync(0xffffffffu, dst, 0, 8);
    bin = __shfl_sync(0xffffffffu, bin, 0, 8);
    if (!valid) return;

    uint4 tw = g_tbf[(size_t)bin * 8 + sub];
    uint4 th = g_hbf[(size_t)src * 8 + sub];
    const __nv_bfloat162* wp = (const __nv_bfloat162*)&tw;
    const __nv_bfloat162* hp = (const __nv_bfloat162*)&th;

    __nv_bfloat162 m0 = __hmul2(wp[0], hp[0]);
    __nv_bfloat162 m1 = __hmul2(wp[1], hp[1]);
    __nv_bfloat162 m2 = __hmul2(wp[2], hp[2]);
    __nv_bfloat162 m3 = __hmul2(wp[3], hp[3]);

    unsigned r0 = *reinterpret_cast<unsigned*>(&m0);
    unsigned r1 = *reinterpret_cast<unsigned*>(&m1);
    unsigned r2 = *reinterpret_cast<unsigned*>(&m2);
    unsigned r3 = *reinterpret_cast<unsigned*>(&m3);

    uint4* dstp = g_aggbf + (size_t)dst * 8 + sub;
    asm volatile("{ .reg .u64 ga; cvta.to.global.u64 ga, %0; "
                 "red.global.add.noftz.v4.bf16x2 [ga], {%1, %2, %3, %4}; }"
                 :: "l"(dstp), "r"(r0), "r"(r1), "r"(r2), "r"(r3) : "memory");
}

// ---------------- kernel 4: fused node tail (fp32 GEMMs; agg loaded as bf16) ------
#define TAIL_SMEM_FLOATS (8192 + 16384 + 16384 + 2048 + 4096 + 4096)
#define TAIL_SMEM_BYTES  (TAIL_SMEM_FLOATS * 4)

__global__ void tail_kernel(const float* __restrict__ x,
                            const float* __restrict__ wA, const float* __restrict__ bA,
                            const float* __restrict__ wB, const float* __restrict__ bB,
                            const float* __restrict__ wC, const float* __restrict__ bC,
                            float* __restrict__ out, int n) {
    extern __shared__ float sm[];
    float* wAs   = sm;
    float* wBs   = wAs + 8192;
    float* wCs   = wBs + 16384;
    float* aggs  = wCs + 16384;
    float* h2s   = aggs + 2048;
    float* h3s   = h2s + 4096;

    int tid = threadIdx.x;
    for (int i = tid; i < 8192;  i += 256) wAs[i] = wA[i];
    for (int i = tid; i < 16384; i += 256) { wBs[i] = wB[i]; wCs[i] = wC[i]; }

    const int fg  = tid & 31;
    const int grp = tid >> 5;
    const int ntiles = (n + 31) >> 5;
    const float4 biasA = make_float4(bA[fg*4+0], bA[fg*4+1], bA[fg*4+2], bA[fg*4+3]);
    const float4 biasB = make_float4(bB[fg*4+0], bB[fg*4+1], bB[fg*4+2], bB[fg*4+3]);
    const float4 biasC = make_float4(bC[fg*4+0], bC[fg*4+1], bC[fg*4+2], bC[fg*4+3]);

    for (int tile = blockIdx.x; tile < ntiles; tile += gridDim.x) {
        int node0 = tile << 5;
        __syncthreads();
        // load agg tile [32][64] bf16 -> fp32 smem : 32 rows x 8 uint4 = 256 loads
        {
            int i = tid;          // exactly 256 threads, 256 chunks
            int r = i >> 3, c = i & 7;
            int node = node0 + r;
            uint4 v = (node < n) ? g_aggbf[(size_t)node * 8 + c]
                                 : make_uint4(0u, 0u, 0u, 0u);
            const __nv_bfloat162* p = (const __nv_bfloat162*)&v;
            float2 f0 = __bfloat1622float2(p[0]);
            float2 f1 = __bfloat1622float2(p[1]);
            float2 f2 = __bfloat1622float2(p[2]);
            float2 f3 = __bfloat1622float2(p[3]);
            float* dst = aggs + r * 64 + c * 8;
            ((float4*)dst)[0] = make_float4(f0.x, f0.y, f1.x, f1.y);
            ((float4*)dst)[1] = make_float4(f2.x, f2.y, f3.x, f3.y);
        }
        __syncthreads();

        {
            float4 acc0 = biasA, acc1 = biasA, acc2 = biasA, acc3 = biasA;
            const float4* in0 = (const float4*)(aggs + (grp * 4 + 0) * 64);
            const float4* in1 = (const float4*)(aggs + (grp * 4 + 1) * 64);
            const float4* in2 = (const float4*)(aggs + (grp * 4 + 2) * 64);
            const float4* in3 = (const float4*)(aggs + (grp * 4 + 3) * 64);
            const float4* wv = (const float4*)wAs;
            #pragma unroll 4
            for (int i4 = 0; i4 < 16; i4++) {
                float4 w0 = wv[(i4*4+0)*32+fg], w1 = wv[(i4*4+1)*32+fg];
                float4 w2 = wv[(i4*4+2)*32+fg], w3 = wv[(i4*4+3)*32+fg];
                float4 a0 = in0[i4], a1 = in1[i4], a2 = in2[i4], a3 = in3[i4];
                acc0.x += a0.x*w0.x + a0.y*w1.x + a0.z*w2.x + a0.w*w3.x;
                acc0.y += a0.x*w0.y + a0.y*w1.y + a0.z*w2.y + a0.w*w3.y;
                acc0.z += a0.x*w0.z + a0.y*w1.z + a0.z*w2.z + a0.w*w3.z;
                acc0.w += a0.x*w0.w + a0.y*w1.w + a0.z*w2.w + a0.w*w3.w;
                acc1.x += a1.x*w0.x + a1.y*w1.x + a1.z*w2.x + a1.w*w3.x;
                acc1.y += a1.x*w0.y + a1.y*w1.y + a1.z*w2.y + a1.w*w3.y;
                acc1.z += a1.x*w0.z + a1.y*w1.z + a1.z*w2.z + a1.w*w3.z;
                acc1.w += a1.x*w0.w + a1.y*w1.w + a1.z*w2.w + a1.w*w3.w;
                acc2.x += a2.x*w0.x + a2.y*w1.x + a2.z*w2.x + a2.w*w3.x;
                acc2.y += a2.x*w0.y + a2.y*w1.y + a2.z*w2.y + a2.w*w3.y;
                acc2.z += a2.x*w0.z + a2.y*w1.z + a2.z*w2.z + a2.w*w3.z;
                acc2.w += a2.x*w0.w + a2.y*w1.w + a2.z*w2.w + a2.w*w3.w;
                acc3.x += a3.x*w0.x + a3.y*w1.x + a3.z*w2.x + a3.w*w3.x;
                acc3.y += a3.x*w0.y + a3.y*w1.y + a3.z*w2.y + a3.w*w3.y;
                acc3.z += a3.x*w0.z + a3.y*w1.z + a3.z*w2.z + a3.w*w3.z;
                acc3.w += a3.x*w0.w + a3.y*w1.w + a3.z*w2.w + a3.w*w3.w;
            }
            ((float4*)(h2s + (grp*4+0)*128))[fg] = make_float4(sspf(acc0.x), sspf(acc0.y), sspf(acc0.z), sspf(acc0.w));
            ((float4*)(h2s + (grp*4+1)*128))[fg] = make_float4(sspf(acc1.x), sspf(acc1.y), sspf(acc1.z), sspf(acc1.w));
            ((float4*)(h2s + (grp*4+2)*128))[fg] = make_float4(sspf(acc2.x), sspf(acc2.y), sspf(acc2.z), sspf(acc2.w));
            ((float4*)(h2s + (grp*4+3)*128))[fg] = make_float4(sspf(acc3.x), sspf(acc3.y), sspf(acc3.z), sspf(acc3.w));
        }
        __syncthreads();

        {
            float4 acc0 = biasB, acc1 = biasB, acc2 = biasB, acc3 = biasB;
            const float4* in0 = (const float4*)(h2s + (grp * 4 + 0) * 128);
            const float4* in1 = (const float4*)(h2s + (grp * 4 + 1) * 128);
            const float4* in2 = (const float4*)(h2s + (grp * 4 + 2) * 128);
            const float4* in3 = (const float4*)(h2s + (grp * 4 + 3) * 128);
            const float4* wv = (const float4*)wBs;
            #pragma unroll 4
            for (int i4 = 0; i4 < 32; i4++) {
                float4 w0 = wv[(i4*4+0)*32+fg], w1 = wv[(i4*4+1)*32+fg];
                float4 w2 = wv[(i4*4+2)*32+fg], w3 = wv[(i4*4+3)*32+fg];
                float4 a0 = in0[i4], a1 = in1[i4], a2 = in2[i4], a3 = in3[i4];
                acc0.x += a0.x*w0.x + a0.y*w1.x + a0.z*w2.x + a0.w*w3.x;
                acc0.y += a0.x*w0.y + a0.y*w1.y + a0.z*w2.y + a0.w*w3.y;
                acc0.z += a0.x*w0.z + a0.y*w1.z + a0.z*w2.z + a0.w*w3.z;
                acc0.w += a0.x*w0.w + a0.y*w1.w + a0.z*w2.w + a0.w*w3.w;
                acc1.x += a1.x*w0.x + a1.y*w1.x + a1.z*w2.x + a1.w*w3.x;
                acc1.y += a1.x*w0.y + a1.y*w1.y + a1.z*w2.y + a1.w*w3.y;
                acc1.z += a1.x*w0.z + a1.y*w1.z + a1.z*w2.z + a1.w*w3.z;
                acc1.w += a1.x*w0.w + a1.y*w1.w + a1.z*w2.w + a1.w*w3.w;
                acc2.x += a2.x*w0.x + a2.y*w1.x + a2.z*w2.x + a2.w*w3.x;
                acc2.y += a2.x*w0.y + a2.y*w1.y + a2.z*w2.y + a2.w*w3.y;
                acc2.z += a2.x*w0.z + a2.y*w1.z + a2.z*w2.z + a2.w*w3.z;
                acc2.w += a2.x*w0.w + a2.y*w1.w + a2.z*w2.w + a2.w*w3.w;
                acc3.x += a3.x*w0.x + a3.y*w1.x + a3.z*w2.x + a3.w*w3.x;
                acc3.y += a3.x*w0.y + a3.y*w1.y + a3.z*w2.y + a3.w*w3.y;
                acc3.z += a3.x*w0.z + a3.y*w1.z + a3.z*w2.z + a3.w*w3.z;
                acc3.w += a3.x*w0.w + a3.y*w1.w + a3.z*w2.w + a3.w*w3.w;
            }
            ((float4*)(h3s + (grp*4+0)*128))[fg] = acc0;
            ((float4*)(h3s + (grp*4+1)*128))[fg] = acc1;
            ((float4*)(h3s + (grp*4+2)*128))[fg] = acc2;
            ((float4*)(h3s + (grp*4+3)*128))[fg] = acc3;
        }
        __syncthreads();

        {
            float4 acc0 = biasC, acc1 = biasC, acc2 = biasC, acc3 = biasC;
            const float4* in0 = (const float4*)(h3s + (grp * 4 + 0) * 128);
            const float4* in1 = (const float4*)(h3s + (grp * 4 + 1) * 128);
            const float4* in2 = (const float4*)(h3s + (grp * 4 + 2) * 128);
            const float4* in3 = (const float4*)(h3s + (grp * 4 + 3) * 128);
            const float4* wv = (const float4*)wCs;
            #pragma unroll 4
            for (int i4 = 0; i4 < 32; i4++) {
                float4 w0 = wv[(i4*4+0)*32+fg], w1 = wv[(i4*4+1)*32+fg];
                float4 w2 = wv[(i4*4+2)*32+fg], w3 = wv[(i4*4+3)*32+fg];
                float4 a0 = in0[i4], a1 = in1[i4], a2 = in2[i4], a3 = in3[i4];
                acc0.x += a0.x*w0.x + a0.y*w1.x + a0.z*w2.x + a0.w*w3.x;
                acc0.y += a0.x*w0.y + a0.y*w1.y + a0.z*w2.y + a0.w*w3.y;
                acc0.z += a0.x*w0.z + a0.y*w1.z + a0.z*w2.z + a0.w*w3.z;
                acc0.w += a0.x*w0.w + a0.y*w1.w + a0.z*w2.w + a0.w*w3.w;
                acc1.x += a1.x*w0.x + a1.y*w1.x + a1.z*w2.x + a1.w*w3.x;
                acc1.y += a1.x*w0.y + a1.y*w1.y + a1.z*w2.y + a1.w*w3.y;
                acc1.z += a1.x*w0.z + a1.y*w1.z + a1.z*w2.z + a1.w*w3.z;
                acc1.w += a1.x*w0.w + a1.y*w1.w + a1.z*w2.w + a1.w*w3.w;
                acc2.x += a2.x*w0.x + a2.y*w1.x + a2.z*w2.x + a2.w*w3.x;
                acc2.y += a2.x*w0.y + a2.y*w1.y + a2.z*w2.y + a2.w*w3.y;
                acc2.z += a2.x*w0.z + a2.y*w1.z + a2.z*w2.z + a2.w*w3.z;
                acc2.w += a2.x*w0.w + a2.y*w1.w + a2.z*w2.w + a2.w*w3.w;
                acc3.x += a3.x*w0.x + a3.y*w1.x + a3.z*w2.x + a3.w*w3.x;
                acc3.y += a3.x*w0.y + a3.y*w1.y + a3.z*w2.y + a3.w*w3.y;
                acc3.z += a3.x*w0.z + a3.y*w1.z + a3.z*w2.z + a3.w*w3.z;
                acc3.w += a3.x*w0.w + a3.y*w1.w + a3.z*w2.w + a3.w*w3.w;
            }
            #pragma unroll
            for (int r = 0; r < 4; r++) {
                int node = node0 + grp * 4 + r;
                if (node >= n) continue;
                float4 acc = (r == 0) ? acc0 : (r == 1) ? acc1 : (r == 2) ? acc2 : acc3;
                float4 xv = ((const float4*)x)[(size_t)node * 32 + fg];
                float4 o;
                o.x = xv.x + fmaxf(acc.x, 0.f);
                o.y = xv.y + fmaxf(acc.y, 0.f);
                o.z = xv.z + fmaxf(acc.z, 0.f);
                o.w = xv.w + fmaxf(acc.w, 0.f);
                ((float4*)out)[(size_t)node * 32 + fg] = o;
            }
        }
    }
}

// ---------------- launcher --------------------------------------------------------
extern "C" void kernel_launch(void* const* d_in, const int* in_sizes, int n_in,
                              void* d_out, int out_size) {
    const float* x        = (const float*)d_in[0];
    const float* pos      = (const float*)d_in[1];
    const int*   ei       = (const int*)d_in[2];
    const float* mlp_w1   = (const float*)d_in[3];
    const float* mlp_b1   = (const float*)d_in[4];
    const float* mlp_w2   = (const float*)d_in[5];
    const float* mlp_b2   = (const float*)d_in[6];
    const float* conv1_w  = (const float*)d_in[7];
    const float* conv2_w  = (const float*)d_in[8];
    const float* conv2_b  = (const float*)d_in[9];
    const float* int_w    = (const float*)d_in[10];
    const float* int_b    = (const float*)d_in[11];
    const float* lin1_w   = (const float*)d_in[12];
    const float* lin1_b   = (const float*)d_in[13];
    float*       out      = (float*)d_out;

    int n = in_sizes[0] / DIMC;
    int E = in_sizes[2] / 2;
    if (n > MAXN) n = MAXN;

    {
        int total = n * 8;
        zero_agg_kernel<<<(total + 255) / 256, 256>>>(n);
        detect_dtype_kernel<<<1, 256>>>(ei, E, n);
    }

    build_table_kernel<<<512, 256>>>(mlp_w1, mlp_b1, mlp_w2, mlp_b2);

    cudaFuncSetAttribute(embed_kernel, cudaFuncAttributeMaxDynamicSharedMemorySize,
                         EMBED_SMEM_BYTES);
    embed_kernel<<<444, 256, EMBED_SMEM_BYTES>>>(x, conv1_w, n);

    // 8 threads per edge -> 32 edges per 256-thread block
    {
        unsigned long long ethreads = (unsigned long long)E * 8ULL;
        unsigned int eblocks = (unsigned int)((ethreads + 255ULL) / 256ULL);
        edge_kernel<<<eblocks, 256>>>(ei, pos, E, n);
    }

    static_assert(TAIL_SMEM_BYTES <= 224 * 1024, "tail smem too large");
    cudaFuncSetAttribute(tail_kernel, cudaFuncAttributeMaxDynamicSharedMemorySize,
                         TAIL_SMEM_BYTES);
    tail_kernel<<<148, 256, TAIL_SMEM_BYTES>>>(x, conv2_w, conv2_b, int_w, int_b,
                                               lin1_w, lin1_b, out, n);
}

// round 9
// speedup vs baseline: 2.8755x; 1.8903x over previous
#include <cuda_runtime.h>
#include <cuda_bf16.h>
#include <math.h>

#define DIMC   128
#define NF     64
#define NG     50
#define NBINS  32768
#define DMAXF  16.0f
#define MAXN   100352
#define LOG2C  0.69314718055994531f
#define CUTOFFF 10.0f

// ---------------- scratch (static device arrays; no runtime alloc) ----------------
__device__ uint4  g_hbf [(size_t)MAXN * 8];     // bf16 h = x @ conv_lin1_w [N,64]
__device__ uint4  g_tbf [(size_t)NBINS * 8];    // bf16 W(d)*C(d) table [NBINS,64]
__device__ uint4  g_aggbf[(size_t)MAXN * 8];    // bf16 segment-summed messages [N,64]
__device__ int    g_is64;

__device__ __forceinline__ float sspf(float v) {
    return fmaxf(v, 0.0f) + log1pf(__expf(-fabsf(v))) - LOG2C;
}

// ---------------- kernel 0a: zero the aggregation buffer --------------------------
__global__ void zero_agg_kernel(int n) {
    int total = n * 8;
    int idx = blockIdx.x * blockDim.x + threadIdx.x;
    if (idx < total)
        g_aggbf[idx] = make_uint4(0u, 0u, 0u, 0u);
}

// ---------------- kernel 0b: detect edge_index dtype ------------------------------
__global__ void detect_dtype_kernel(const int* __restrict__ ei, int E, int n) {
    __shared__ int bad;
    if (threadIdx.x == 0) bad = 0;
    __syncthreads();
    for (int i = threadIdx.x; i < 1024; i += blockDim.x) {
        long long e = ((long long)i * (long long)E) / 1024LL;
        int lo = ei[2 * e];
        int hi = ei[2 * e + 1];
        if (hi != 0 || lo < 0 || lo >= n) atomicExch(&bad, 1);
    }
    __syncthreads();
    if (threadIdx.x == 0) g_is64 = bad ? 0 : 1;
}

// ---------------- kernel 1: build W(d)*C(d) table (bf16 output) -------------------
__global__ void build_table_kernel(const float* __restrict__ w1, const float* __restrict__ b1,
                                   const float* __restrict__ w2, const float* __restrict__ b2) {
    __shared__ float w1s[NG * NF];
    __shared__ float w2s[NF * NF];
    __shared__ float b1s[NF], b2s[NF];
    __shared__ float attr[4][NG];
    __shared__ float f1s [4][NF];

    int tid = threadIdx.x;
    for (int i = tid; i < NG * NF; i += 256) w1s[i] = w1[i];
    for (int i = tid; i < NF * NF; i += 256) w2s[i] = w2[i];
    if (tid < NF) { b1s[tid] = b1[tid]; b2s[tid] = b2[tid]; }
    __syncthreads();

    const int grp = tid >> 6;
    const int f   = tid & 63;
    const float delta    = DMAXF / (float)(NBINS - 1);
    const float off_step = CUTOFFF / (float)(NG - 1);
    const float coeff    = -0.5f / (off_step * off_step);
    __nv_bfloat16* tab = (__nv_bfloat16*)g_tbf;

    for (int base = blockIdx.x * 4; base < NBINS; base += gridDim.x * 4) {
        int bin = base + grp;
        float d = (float)bin * delta;

        if (f < NG) {
            float t = d - (float)f * off_step;
            attr[grp][f] = __expf(coeff * t * t);
        }
        __syncthreads();

        float z = b1s[f];
        #pragma unroll
        for (int g = 0; g < NG; g++) z += attr[grp][g] * w1s[g * NF + f];
        f1s[grp][f] = sspf(z);
        __syncthreads();

        float wv = b2s[f];
        #pragma unroll
        for (int i = 0; i < NF; i++) wv += f1s[grp][i] * w2s[i * NF + f];

        float C = 0.5f * (cosf(d * 0.31415926535897932f) + 1.0f);
        tab[(size_t)bin * NF + f] = __float2bfloat16(wv * C);
        __syncthreads();
    }
}

// ---------------- kernel 2: node embed h = x @ conv_lin1_w  [N,64] (bf16 out) -----
#define ETILE 64
#define EMBED_SMEM_BYTES ((DIMC * 16 + ETILE * 32) * 16)

__global__ void embed_kernel(const float* __restrict__ x, const float* __restrict__ w, int n) {
    extern __shared__ float4 esm[];
    float4* ws = esm;
    float4* xs = esm + DIMC * 16;

    int tid = threadIdx.x;
    for (int i = tid; i < DIMC * 16; i += 256) ws[i] = ((const float4*)w)[i];

    const int fg = tid & 15;
    const int nr = tid >> 4;
    const int ntiles = (n + ETILE - 1) / ETILE;
    uint2* hb = (uint2*)g_hbf;

    for (int tile = blockIdx.x; tile < ntiles; tile += gridDim.x) {
        int node0 = tile * ETILE;
        __syncthreads();
        for (int i = tid; i < ETILE * 32; i += 256) {
            int node = node0 + (i >> 5);
            xs[i] = (node < n) ? ((const float4*)x)[(size_t)node * 32 + (i & 31)]
                               : make_float4(0.f, 0.f, 0.f, 0.f);
        }
        __syncthreads();

        float4 acc0 = make_float4(0.f,0.f,0.f,0.f), acc1 = acc0, acc2 = acc0, acc3 = acc0;
        const float4* xr0 = xs + (nr * 4 + 0) * 32;
        const float4* xr1 = xs + (nr * 4 + 1) * 32;
        const float4* xr2 = xs + (nr * 4 + 2) * 32;
        const float4* xr3 = xs + (nr * 4 + 3) * 32;

        #pragma unroll 4
        for (int k4 = 0; k4 < 32; k4++) {
            float4 w0 = ws[(k4 * 4 + 0) * 16 + fg];
            float4 w1 = ws[(k4 * 4 + 1) * 16 + fg];
            float4 w2 = ws[(k4 * 4 + 2) * 16 + fg];
            float4 w3 = ws[(k4 * 4 + 3) * 16 + fg];
            float4 a0 = xr0[k4], a1 = xr1[k4], a2 = xr2[k4], a3 = xr3[k4];

            acc0.x += a0.x*w0.x + a0.y*w1.x + a0.z*w2.x + a0.w*w3.x;
            acc0.y += a0.x*w0.y + a0.y*w1.y + a0.z*w2.y + a0.w*w3.y;
            acc0.z += a0.x*w0.z + a0.y*w1.z + a0.z*w2.z + a0.w*w3.z;
            acc0.w += a0.x*w0.w + a0.y*w1.w + a0.z*w2.w + a0.w*w3.w;

            acc1.x += a1.x*w0.x + a1.y*w1.x + a1.z*w2.x + a1.w*w3.x;
            acc1.y += a1.x*w0.y + a1.y*w1.y + a1.z*w2.y + a1.w*w3.y;
            acc1.z += a1.x*w0.z + a1.y*w1.z + a1.z*w2.z + a1.w*w3.z;
            acc1.w += a1.x*w0.w + a1.y*w1.w + a1.z*w2.w + a1.w*w3.w;

            acc2.x += a2.x*w0.x + a2.y*w1.x + a2.z*w2.x + a2.w*w3.x;
            acc2.y += a2.x*w0.y + a2.y*w1.y + a2.z*w2.y + a2.w*w3.y;
            acc2.z += a2.x*w0.z + a2.y*w1.z + a2.z*w2.z + a2.w*w3.z;
            acc2.w += a2.x*w0.w + a2.y*w1.w + a2.z*w2.w + a2.w*w3.w;

            acc3.x += a3.x*w0.x + a3.y*w1.x + a3.z*w2.x + a3.w*w3.x;
            acc3.y += a3.x*w0.y + a3.y*w1.y + a3.z*w2.y + a3.w*w3.y;
            acc3.z += a3.x*w0.z + a3.y*w1.z + a3.z*w2.z + a3.w*w3.z;
            acc3.w += a3.x*w0.w + a3.y*w1.w + a3.z*w2.w + a3.w*w3.w;
        }

        #pragma unroll
        for (int r = 0; r < 4; r++) {
            int node = node0 + nr * 4 + r;
            if (node >= n) continue;
            float4 a = (r == 0) ? acc0 : (r == 1) ? acc1 : (r == 2) ? acc2 : acc3;
            __nv_bfloat162 p0 = __floats2bfloat162_rn(a.x, a.y);
            __nv_bfloat162 p1 = __floats2bfloat162_rn(a.z, a.w);
            uint2 v;
            v.x = *reinterpret_cast<unsigned*>(&p0);
            v.y = *reinterpret_cast<unsigned*>(&p1);
            hb[(size_t)node * 16 + fg] = v;
        }
    }
}

// ---------------- kernel 3: per-edge message + scatter (unchanged from R8) --------
__global__ void edge_kernel(const int* __restrict__ ei,
                            const float* __restrict__ pos, int E, int n) {
    int lane = threadIdx.x & 31;
    int sub  = lane & 7;
    long long t = (long long)blockIdx.x * blockDim.x + threadIdx.x;
    long long e = t >> 3;
    bool valid = (e < (long long)E);

    int src = 0, dst = 0, bin = 0;
    if (sub == 0 && valid) {
        if (g_is64) { src = ei[2 * (size_t)e]; dst = ei[2 * ((size_t)E + e)]; }
        else        { src = ei[(size_t)e];     dst = ei[(size_t)E + e];       }
        src = min(max(src, 0), n - 1);
        dst = min(max(dst, 0), n - 1);
        float dx = pos[dst * 3 + 0] - pos[src * 3 + 0];
        float dy = pos[dst * 3 + 1] - pos[src * 3 + 1];
        float dz = pos[dst * 3 + 2] - pos[src * 3 + 2];
        float d  = sqrtf(dx * dx + dy * dy + dz * dz);
        float u = d * ((float)(NBINS - 1) / DMAXF);
        bin = __float2int_rn(u);
        if (bin > NBINS - 1) bin = NBINS - 1;
    }
    src = __shfl_sync(0xffffffffu, src, 0, 8);
    dst = __shfl_sync(0xffffffffu, dst, 0, 8);
    bin = __shfl_sync(0xffffffffu, bin, 0, 8);
    if (!valid) return;

    uint4 tw = g_tbf[(size_t)bin * 8 + sub];
    uint4 th = g_hbf[(size_t)src * 8 + sub];
    const __nv_bfloat162* wp = (const __nv_bfloat162*)&tw;
    const __nv_bfloat162* hp = (const __nv_bfloat162*)&th;

    __nv_bfloat162 m0 = __hmul2(wp[0], hp[0]);
    __nv_bfloat162 m1 = __hmul2(wp[1], hp[1]);
    __nv_bfloat162 m2 = __hmul2(wp[2], hp[2]);
    __nv_bfloat162 m3 = __hmul2(wp[3], hp[3]);

    unsigned r0 = *reinterpret_cast<unsigned*>(&m0);
    unsigned r1 = *reinterpret_cast<unsigned*>(&m1);
    unsigned r2 = *reinterpret_cast<unsigned*>(&m2);
    unsigned r3 = *reinterpret_cast<unsigned*>(&m3);

    uint4* dstp = g_aggbf + (size_t)dst * 8 + sub;
    asm volatile("{ .reg .u64 ga; cvta.to.global.u64 ga, %0; "
                 "red.global.add.noftz.v4.bf16x2 [ga], {%1, %2, %3, %4}; }"
                 :: "l"(dstp), "r"(r0), "r"(r1), "r"(r2), "r"(r3) : "memory");
}

// ---------------- kernel 4: fused node tail via bf16 tensor cores -----------------
// h2 = ssp(agg @ wA + bA); h3 = h2 @ wB + bB; out = x + relu(h3 @ wC + bC)
// mma.sync.m16n8k16 bf16 -> fp32 accumulators; epilogues in fp32.
#define BUFP 136      // padded pitch (bf16 elems) for 128-wide buffers
#define INAP 72       // padded pitch for 64-wide agg tile
#define TAILM_SMEM_ELEMS (64*BUFP + 2*128*BUFP + 32*INAP + 2*32*BUFP)
#define TAILM_SMEM_BYTES (TAILM_SMEM_ELEMS * 2)

#define LDSM_X4(R0,R1,R2,R3,ADDR) \
    asm volatile("ldmatrix.sync.aligned.m8n8.x4.shared.b16 {%0,%1,%2,%3}, [%4];" \
        : "=r"(R0), "=r"(R1), "=r"(R2), "=r"(R3) : "r"(ADDR))
#define LDSM_X4T(R0,R1,R2,R3,ADDR) \
    asm volatile("ldmatrix.sync.aligned.m8n8.x4.trans.shared.b16 {%0,%1,%2,%3}, [%4];" \
        : "=r"(R0), "=r"(R1), "=r"(R2), "=r"(R3) : "r"(ADDR))
#define MMA_BF16(C, A0,A1,A2,A3, B0,B1) \
    asm volatile("mma.sync.aligned.m16n8k16.row.col.f32.bf16.bf16.f32 " \
        "{%0,%1,%2,%3}, {%4,%5,%6,%7}, {%8,%9}, {%0,%1,%2,%3};" \
        : "+f"((C)[0]), "+f"((C)[1]), "+f"((C)[2]), "+f"((C)[3]) \
        : "r"(A0), "r"(A1), "r"(A2), "r"(A3), "r"(B0), "r"(B1))

__global__ void tail_mma_kernel(const float* __restrict__ x,
                                const float* __restrict__ wA, const float* __restrict__ bA,
                                const float* __restrict__ wB, const float* __restrict__ bB,
                                const float* __restrict__ wC, const float* __restrict__ bC,
                                float* __restrict__ out, int n) {
    extern __shared__ __align__(16) __nv_bfloat16 tsm[];
    __nv_bfloat16* wAb  = tsm;                    // [64][BUFP]
    __nv_bfloat16* wBb  = wAb + 64 * BUFP;        // [128][BUFP]
    __nv_bfloat16* wCb  = wBb + 128 * BUFP;       // [128][BUFP]
    __nv_bfloat16* inA  = wCb + 128 * BUFP;       // [32][INAP]
    __nv_bfloat16* buf1 = inA + 32 * INAP;        // [32][BUFP]
    __nv_bfloat16* buf2 = buf1 + 32 * BUFP;       // [32][BUFP]

    const int tid  = threadIdx.x;
    const int lane = tid & 31;
    const int warp = tid >> 5;

    // convert weights to bf16 smem (once)
    for (int i = tid; i < 64 * 128; i += 256)
        wAb[(i >> 7) * BUFP + (i & 127)] = __float2bfloat16(wA[i]);
    for (int i = tid; i < 128 * 128; i += 256) {
        int r = i >> 7, c = i & 127;
        wBb[r * BUFP + c] = __float2bfloat16(wB[i]);
        wCb[r * BUFP + c] = __float2bfloat16(wC[i]);
    }

    const int warpm = warp >> 2;                  // 0..1 : 16-row slab
    const int warpn = warp & 3;                   // 0..3 : 32-col slab
    const int lrow  = ((lane >> 3) & 1) * 8 + (lane & 7);   // ldmatrix row-dim offset
    const int lcol8 = (lane >> 4) * 8;                       // ldmatrix col-dim offset
    const int crow  = lane >> 2;                  // C-frag row 0..7
    const int ccol  = (lane & 3) * 2;             // C-frag col (even)

    const unsigned inA_s = (unsigned)__cvta_generic_to_shared(inA);
    const unsigned b1_s  = (unsigned)__cvta_generic_to_shared(buf1);
    const unsigned b2_s  = (unsigned)__cvta_generic_to_shared(buf2);
    const unsigned wA_s  = (unsigned)__cvta_generic_to_shared(wAb);
    const unsigned wB_s  = (unsigned)__cvta_generic_to_shared(wBb);
    const unsigned wC_s  = (unsigned)__cvta_generic_to_shared(wCb);

    const int ntiles = (n + 31) >> 5;
    for (int tile = blockIdx.x; tile < ntiles; tile += gridDim.x) {
        int node0 = tile << 5;
        __syncthreads();                          // protect smem from previous tile
        {   // load agg tile [32][64] bf16 (direct copy, already bf16)
            int r = tid >> 3, c = tid & 7;
            int node = node0 + r;
            uint4 v = (node < n) ? g_aggbf[(size_t)node * 8 + c] : make_uint4(0u,0u,0u,0u);
            *(uint4*)(inA + r * INAP + c * 8) = v;
        }
        __syncthreads();

        float c4[4][4];

        // ---- stage A: [32,64] @ wA[64,128], ssp epilogue -> buf1 ----
        #pragma unroll
        for (int nb = 0; nb < 4; nb++)
            #pragma unroll
            for (int j = 0; j < 4; j++) c4[nb][j] = 0.f;
        #pragma unroll
        for (int k0 = 0; k0 < 64; k0 += 16) {
            unsigned a0,a1,a2,a3;
            LDSM_X4(a0,a1,a2,a3, inA_s + (unsigned)(((warpm*16 + lrow)*INAP + k0 + lcol8) << 1));
            #pragma unroll
            for (int nb2 = 0; nb2 < 2; nb2++) {
                unsigned q0,q1,q2,q3;
                LDSM_X4T(q0,q1,q2,q3, wA_s + (unsigned)(((k0 + lrow)*BUFP + warpn*32 + nb2*16 + lcol8) << 1));
                MMA_BF16(c4[nb2*2+0], a0,a1,a2,a3, q0,q1);
                MMA_BF16(c4[nb2*2+1], a0,a1,a2,a3, q2,q3);
            }
        }
        #pragma unroll
        for (int nb = 0; nb < 4; nb++) {
            int col = warpn*32 + nb*8 + ccol;
            float2 bb = *(const float2*)(bA + col);
            int r0 = warpm*16 + crow;
            __nv_bfloat162 p0 = __floats2bfloat162_rn(sspf(c4[nb][0] + bb.x), sspf(c4[nb][1] + bb.y));
            __nv_bfloat162 p1 = __floats2bfloat162_rn(sspf(c4[nb][2] + bb.x), sspf(c4[nb][3] + bb.y));
            *(__nv_bfloat162*)(buf1 + r0 * BUFP + col) = p0;
            *(__nv_bfloat162*)(buf1 + (r0 + 8) * BUFP + col) = p1;
        }
        __syncthreads();

        // ---- stage B: buf1[32,128] @ wB[128,128] -> buf2 ----
        #pragma unroll
        for (int nb = 0; nb < 4; nb++)
            #pragma unroll
            for (int j = 0; j < 4; j++) c4[nb][j] = 0.f;
        #pragma unroll
        for (int k0 = 0; k0 < 128; k0 += 16) {
            unsigned a0,a1,a2,a3;
            LDSM_X4(a0,a1,a2,a3, b1_s + (unsigned)(((warpm*16 + lrow)*BUFP + k0 + lcol8) << 1));
            #pragma unroll
            for (int nb2 = 0; nb2 < 2; nb2++) {
                unsigned q0,q1,q2,q3;
                LDSM_X4T(q0,q1,q2,q3, wB_s + (unsigned)(((k0 + lrow)*BUFP + warpn*32 + nb2*16 + lcol8) << 1));
                MMA_BF16(c4[nb2*2+0], a0,a1,a2,a3, q0,q1);
                MMA_BF16(c4[nb2*2+1], a0,a1,a2,a3, q2,q3);
            }
        }
        #pragma unroll
        for (int nb = 0; nb < 4; nb++) {
            int col = warpn*32 + nb*8 + ccol;
            float2 bb = *(const float2*)(bB + col);
            int r0 = warpm*16 + crow;
            __nv_bfloat162 p0 = __floats2bfloat162_rn(c4[nb][0] + bb.x, c4[nb][1] + bb.y);
            __nv_bfloat162 p1 = __floats2bfloat162_rn(c4[nb][2] + bb.x, c4[nb][3] + bb.y);
            *(__nv_bfloat162*)(buf2 + r0 * BUFP + col) = p0;
            *(__nv_bfloat162*)(buf2 + (r0 + 8) * BUFP + col) = p1;
        }
        __syncthreads();

        // ---- stage C: buf2[32,128] @ wC[128,128], relu + x -> out ----
        #pragma unroll
        for (int nb = 0; nb < 4; nb++)
            #pragma unroll
            for (int j = 0; j < 4; j++) c4[nb][j] = 0.f;
        #pragma unroll
        for (int k0 = 0; k0 < 128; k0 += 16) {
            unsigned a0,a1,a2,a3;
            LDSM_X4(a0,a1,a2,a3, b2_s + (unsigned)(((warpm*16 + lrow)*BUFP + k0 + lcol8) << 1));
            #pragma unroll
            for (int nb2 = 0; nb2 < 2; nb2++) {
                unsigned q0,q1,q2,q3;
                LDSM_X4T(q0,q1,q2,q3, wC_s + (unsigned)(((k0 + lrow)*BUFP + warpn*32 + nb2*16 + lcol8) << 1));
                MMA_BF16(c4[nb2*2+0], a0,a1,a2,a3, q0,q1);
                MMA_BF16(c4[nb2*2+1], a0,a1,a2,a3, q2,q3);
            }
        }
        #pragma unroll
        for (int nb = 0; nb < 4; nb++) {
            int col = warpn*32 + nb*8 + ccol;
            float2 bb = *(const float2*)(bC + col);
            int r0 = node0 + warpm*16 + crow;
            if (r0 < n) {
                float2 xv = *(const float2*)(x + (size_t)r0 * DIMC + col);
                float2 o;
                o.x = xv.x + fmaxf(c4[nb][0] + bb.x, 0.f);
                o.y = xv.y + fmaxf(c4[nb][1] + bb.y, 0.f);
                *(float2*)(out + (size_t)r0 * DIMC + col) = o;
            }
            int r1 = r0 + 8;
            if (r1 < n) {
                float2 xv = *(const float2*)(x + (size_t)r1 * DIMC + col);
                float2 o;
                o.x = xv.x + fmaxf(c4[nb][2] + bb.x, 0.f);
                o.y = xv.y + fmaxf(c4[nb][3] + bb.y, 0.f);
                *(float2*)(out + (size_t)r1 * DIMC + col) = o;
            }
        }
    }
}

// ---------------- launcher --------------------------------------------------------
extern "C" void kernel_launch(void* const* d_in, const int* in_sizes, int n_in,
                              void* d_out, int out_size) {
    const float* x        = (const float*)d_in[0];
    const float* pos      = (const float*)d_in[1];
    const int*   ei       = (const int*)d_in[2];
    const float* mlp_w1   = (const float*)d_in[3];
    const float* mlp_b1   = (const float*)d_in[4];
    const float* mlp_w2   = (const float*)d_in[5];
    const float* mlp_b2   = (const float*)d_in[6];
    const float* conv1_w  = (const float*)d_in[7];
    const float* conv2_w  = (const float*)d_in[8];
    const float* conv2_b  = (const float*)d_in[9];
    const float* int_w    = (const float*)d_in[10];
    const float* int_b    = (const float*)d_in[11];
    const float* lin1_w   = (const float*)d_in[12];
    const float* lin1_b   = (const float*)d_in[13];
    float*       out      = (float*)d_out;

    int n = in_sizes[0] / DIMC;
    int E = in_sizes[2] / 2;
    if (n > MAXN) n = MAXN;

    {
        int total = n * 8;
        zero_agg_kernel<<<(total + 255) / 256, 256>>>(n);
        detect_dtype_kernel<<<1, 256>>>(ei, E, n);
    }

    build_table_kernel<<<512, 256>>>(mlp_w1, mlp_b1, mlp_w2, mlp_b2);

    cudaFuncSetAttribute(embed_kernel, cudaFuncAttributeMaxDynamicSharedMemorySize,
                         EMBED_SMEM_BYTES);
    embed_kernel<<<444, 256, EMBED_SMEM_BYTES>>>(x, conv1_w, n);

    {
        unsigned long long ethreads = (unsigned long long)E * 8ULL;
        unsigned int eblocks = (unsigned int)((ethreads + 255ULL) / 256ULL);
        edge_kernel<<<eblocks, 256>>>(ei, pos, E, n);
    }

    static_assert(TAILM_SMEM_BYTES <= 224 * 1024, "tail smem too large");
    cudaFuncSetAttribute(tail_mma_kernel, cudaFuncAttributeMaxDynamicSharedMemorySize,
                         TAILM_SMEM_BYTES);
    tail_mma_kernel<<<296, 256, TAILM_SMEM_BYTES>>>(x, conv2_w, conv2_b, int_w, int_b,
                                                    lin1_w, lin1_b, out, n);
}